// round 2
// baseline (speedup 1.0000x reference)
#include <cuda_runtime.h>
#include <math.h>

#define N_NODES 50000
#define DIM     128

// ---------------- scratch (device globals; no allocation allowed) -------------
// typ: 0 = user, 1 = news
__device__ __align__(16) float g_aggx [2][N_NODES * DIM];
__device__ __align__(16) float g_aggh [2][N_NODES * DIM];
__device__ __align__(16) float g_agghr[2][N_NODES * DIM];
__device__ __align__(16) float g_z    [2][N_NODES * DIM];
__device__ __align__(16) float g_hr   [2][N_NODES * DIM];
__device__ __align__(16) float g_cx   [2][N_NODES * DIM];
__device__ float g_deg[2][N_NODES];
__device__ __align__(16) float g_Wbig[2][512 * 384];   // [aggx|x|aggh|h] -> [z|r|cx]
__device__ __align__(16) float g_W5  [2][256 * 128];   // [agghr|hr] -> ch
__device__ float g_bias [2][3][DIM];                   // z, r, cx biases
__device__ float g_bias5[2][DIM];

// ---------------- zero scratch -------------------------------------------------
__global__ void k_zero() {
    int idx = blockIdx.x * blockDim.x + threadIdx.x;
    if (idx < N_NODES * DIM) {
        g_aggx[0][idx] = 0.f; g_aggx[1][idx] = 0.f;
        g_aggh[0][idx] = 0.f; g_aggh[1][idx] = 0.f;
        g_agghr[0][idx] = 0.f; g_agghr[1][idx] = 0.f;
    }
    if (idx < N_NODES) { g_deg[0][idx] = 0.f; g_deg[1][idx] = 0.f; }
}

// ---------------- degree histogram ---------------------------------------------
__global__ void k_deg(const int* __restrict__ dst_un, const int* __restrict__ dst_nu, int E) {
    int e = blockIdx.x * blockDim.x + threadIdx.x;
    if (e < E) {
        atomicAdd(&g_deg[1][dst_un[e]], 1.f);   // news is dst of un edges
        atomicAdd(&g_deg[0][dst_nu[e]], 1.f);   // user is dst of nu edges
    }
}

// ---------------- scatter x & h features (one warp per edge, float4 atomics) ----
template <int TYP>
__global__ void k_scatter_xh(const float* __restrict__ xsrc, const float* __restrict__ hsrc,
                             const int* __restrict__ src, const int* __restrict__ dst, int E) {
    long t = (long)blockIdx.x * blockDim.x + threadIdx.x;
    int e = (int)(t >> 5);
    int lane = (int)(t & 31);
    if (e >= E) return;
    int s = __ldg(src + e);
    int d = __ldg(dst + e);
    float4 vx = ((const float4*)(xsrc + (size_t)s * DIM))[lane];
    float4 vh = ((const float4*)(hsrc + (size_t)s * DIM))[lane];
    atomicAdd(((float4*)(g_aggx[TYP] + (size_t)d * DIM)) + lane, vx);
    atomicAdd(((float4*)(g_aggh[TYP] + (size_t)d * DIM)) + lane, vh);
}

// ---------------- scatter h*r features ------------------------------------------
template <int TYP>
__global__ void k_scatter_hr(const int* __restrict__ src, const int* __restrict__ dst, int E) {
    long t = (long)blockIdx.x * blockDim.x + threadIdx.x;
    int e = (int)(t >> 5);
    int lane = (int)(t & 31);
    if (e >= E) return;
    int s = __ldg(src + e);
    int d = __ldg(dst + e);
    const float* f = g_hr[1 - TYP];   // source features are the *other* node type's h*r
    float4 v = ((const float4*)(f + (size_t)s * DIM))[lane];
    atomicAdd(((float4*)(g_agghr[TYP] + (size_t)d * DIM)) + lane, v);
}

// ---------------- normalize sums -> means ----------------------------------------
template <int WHICH>   // 0: aggx+aggh, 1: agghr
__global__ void k_norm() {
    int idx = blockIdx.x * blockDim.x + threadIdx.x;
    if (idx >= N_NODES * DIM) return;
    int row = idx >> 7;
    float i0 = 1.f / fmaxf(g_deg[0][row], 1.f);
    float i1 = 1.f / fmaxf(g_deg[1][row], 1.f);
    if (WHICH == 0) {
        g_aggx[0][idx] *= i0; g_aggh[0][idx] *= i0;
        g_aggx[1][idx] *= i1; g_aggh[1][idx] *= i1;
    } else {
        g_agghr[0][idx] *= i0;
        g_agghr[1][idx] *= i1;
    }
}

// ---------------- weight / bias repack --------------------------------------------
// Wl, Wr: [6][2][128][128]; b: [6][2][128]
// Wbig[t] rows: 0-127 aggx, 128-255 x, 256-383 aggh, 384-511 h
// Wbig[t] cols: 0-127 z-pre, 128-255 r-pre, 256-383 cx  (aggh/h rows zero for cx)
__global__ void k_repack(const float* __restrict__ Wl, const float* __restrict__ Wr,
                         const float* __restrict__ b) {
    int idx = blockIdx.x * blockDim.x + threadIdx.x;
    const int TOT_BIG = 2 * 512 * 384;
    const int TOT_W5  = 2 * 256 * 128;
    if (idx < TOT_BIG) {
        int t = idx / (512 * 384);
        int rem = idx % (512 * 384);
        int r = rem / 384, c = rem % 384;
        int wi = 1 - t;                    // user outputs use weight index 1, news 0
        int rb = r >> 7, rr = r & 127;
        int cb = c >> 7, cc = c & 127;
        float v = 0.f;
        if (rb == 0)      { int g = cb * 2;     v = Wl[((g * 2 + wi) * 128 + rr) * 128 + cc]; }
        else if (rb == 1) { int g = cb * 2;     v = Wr[((g * 2 + wi) * 128 + rr) * 128 + cc]; }
        else if (rb == 2) { if (cb < 2) { int g = cb * 2 + 1; v = Wl[((g * 2 + wi) * 128 + rr) * 128 + cc]; } }
        else              { if (cb < 2) { int g = cb * 2 + 1; v = Wr[((g * 2 + wi) * 128 + rr) * 128 + cc]; } }
        g_Wbig[t][r * 384 + c] = v;
        return;
    }
    int i2 = idx - TOT_BIG;
    if (i2 < TOT_W5) {
        int t = i2 / (256 * 128);
        int rem = i2 % (256 * 128);
        int r = rem / 128, c = rem % 128;
        int wi = 1 - t;
        float v = (r < 128) ? Wl[((5 * 2 + wi) * 128 + r) * 128 + c]
                            : Wr[((5 * 2 + wi) * 128 + (r - 128)) * 128 + c];
        g_W5[t][r * 128 + c] = v;
        return;
    }
    int i3 = i2 - TOT_W5;
    if (i3 < 2 * 128) {
        int t = i3 / 128, c = i3 % 128;
        int wi = 1 - t;
        g_bias[t][0][c] = b[(0 * 2 + wi) * 128 + c] + b[(1 * 2 + wi) * 128 + c];
        g_bias[t][1][c] = b[(2 * 2 + wi) * 128 + c] + b[(3 * 2 + wi) * 128 + c];
        g_bias[t][2][c] = b[(4 * 2 + wi) * 128 + c];
        g_bias5[t][c]   = b[(5 * 2 + wi) * 128 + c];
    }
}

__device__ __forceinline__ float sigmoidf_(float v) { return 1.f / (1.f + expf(-v)); }

// ---------------- fused GEMM pass A: [aggx|x|aggh|h](512) @ Wbig(512x384) ---------
// col tile 0 -> z = sigmoid(.)   ; col tile 1 -> r = sigmoid(.), store hr = h*r
// col tile 2 -> cx               . BM=BN=128, BK=16, 256 threads, 8x8 per thread.
template <int TYP>
__global__ void __launch_bounds__(256) k_gemmA(const float* __restrict__ xself,
                                               const float* __restrict__ hself) {
    __shared__ float As[16][128];
    __shared__ float Bs[16][128];
    int tid = threadIdx.x;
    int tx = tid & 15, ty = tid >> 4;
    int rowBase = blockIdx.x * 128;
    int ct = blockIdx.y;
    int colBase = ct * 128;

    const float* aggx = g_aggx[TYP];
    const float* aggh = g_aggh[TYP];
    const float* Wb = g_Wbig[TYP];

    float acc[8][8];
#pragma unroll
    for (int i = 0; i < 8; i++)
#pragma unroll
        for (int j = 0; j < 8; j++) acc[i][j] = 0.f;

    for (int kt = 0; kt < 32; ++kt) {
        int srcm = kt >> 3;
        const float* Asrc = (srcm == 0) ? aggx : (srcm == 1) ? xself : (srcm == 2) ? aggh : hself;
        int kcol = (kt & 7) * 16;
#pragma unroll
        for (int i = 0; i < 2; i++) {
            int row = i * 64 + (tid >> 2);
            int kq = (tid & 3) * 4;
            int grow = rowBase + row;
            float4 v = make_float4(0.f, 0.f, 0.f, 0.f);
            if (grow < N_NODES) v = *(const float4*)(Asrc + (size_t)grow * 128 + kcol + kq);
            As[kq + 0][row] = v.x; As[kq + 1][row] = v.y;
            As[kq + 2][row] = v.z; As[kq + 3][row] = v.w;
        }
#pragma unroll
        for (int i = 0; i < 2; i++) {
            int r = i * 8 + (tid >> 5);
            int c = (tid & 31) * 4;
            float4 v = *(const float4*)(Wb + (size_t)(kt * 16 + r) * 384 + colBase + c);
            *(float4*)(&Bs[r][c]) = v;
        }
        __syncthreads();
#pragma unroll
        for (int kk = 0; kk < 16; kk++) {
            float a[8], bb[8];
#pragma unroll
            for (int i = 0; i < 8; i++) a[i] = As[kk][ty * 8 + i];
#pragma unroll
            for (int j = 0; j < 8; j++) bb[j] = Bs[kk][tx * 8 + j];
#pragma unroll
            for (int i = 0; i < 8; i++)
#pragma unroll
                for (int j = 0; j < 8; j++) acc[i][j] += a[i] * bb[j];
        }
        __syncthreads();
    }

    const float* bias = g_bias[TYP][ct];
#pragma unroll
    for (int i = 0; i < 8; i++) {
        int grow = rowBase + ty * 8 + i;
        if (grow >= N_NODES) continue;
#pragma unroll
        for (int j = 0; j < 8; j++) {
            int c = tx * 8 + j;
            float v = acc[i][j] + bias[c];
            size_t off = (size_t)grow * 128 + c;
            if (ct == 0) {
                g_z[TYP][off] = sigmoidf_(v);
            } else if (ct == 1) {
                float r = sigmoidf_(v);
                g_hr[TYP][off] = hself[off] * r;
            } else {
                g_cx[TYP][off] = v;
            }
        }
    }
}

// ---------------- fused GEMM pass B: [agghr|hr](256) @ W5(256x128) + GRU blend ----
template <int TYP>
__global__ void __launch_bounds__(256) k_gemmB(const float* __restrict__ hself,
                                               float* __restrict__ out) {
    __shared__ float As[16][128];
    __shared__ float Bs[16][128];
    int tid = threadIdx.x;
    int tx = tid & 15, ty = tid >> 4;
    int rowBase = blockIdx.x * 128;

    const float* agghr = g_agghr[TYP];
    const float* hrs = g_hr[TYP];
    const float* W = g_W5[TYP];

    float acc[8][8];
#pragma unroll
    for (int i = 0; i < 8; i++)
#pragma unroll
        for (int j = 0; j < 8; j++) acc[i][j] = 0.f;

    for (int kt = 0; kt < 16; ++kt) {
        const float* Asrc = (kt < 8) ? agghr : hrs;
        int kcol = (kt & 7) * 16;
#pragma unroll
        for (int i = 0; i < 2; i++) {
            int row = i * 64 + (tid >> 2);
            int kq = (tid & 3) * 4;
            int grow = rowBase + row;
            float4 v = make_float4(0.f, 0.f, 0.f, 0.f);
            if (grow < N_NODES) v = *(const float4*)(Asrc + (size_t)grow * 128 + kcol + kq);
            As[kq + 0][row] = v.x; As[kq + 1][row] = v.y;
            As[kq + 2][row] = v.z; As[kq + 3][row] = v.w;
        }
#pragma unroll
        for (int i = 0; i < 2; i++) {
            int r = i * 8 + (tid >> 5);
            int c = (tid & 31) * 4;
            float4 v = *(const float4*)(W + (size_t)(kt * 16 + r) * 128 + c);
            *(float4*)(&Bs[r][c]) = v;
        }
        __syncthreads();
#pragma unroll
        for (int kk = 0; kk < 16; kk++) {
            float a[8], bb[8];
#pragma unroll
            for (int i = 0; i < 8; i++) a[i] = As[kk][ty * 8 + i];
#pragma unroll
            for (int j = 0; j < 8; j++) bb[j] = Bs[kk][tx * 8 + j];
#pragma unroll
            for (int i = 0; i < 8; i++)
#pragma unroll
                for (int j = 0; j < 8; j++) acc[i][j] += a[i] * bb[j];
        }
        __syncthreads();
    }

    const float* bias = g_bias5[TYP];
#pragma unroll
    for (int i = 0; i < 8; i++) {
        int grow = rowBase + ty * 8 + i;
        if (grow >= N_NODES) continue;
#pragma unroll
        for (int j = 0; j < 8; j++) {
            int c = tx * 8 + j;
            size_t off = (size_t)grow * 128 + c;
            float ch = acc[i][j] + bias[c];
            float ht = tanhf(g_cx[TYP][off] + ch);
            float z = g_z[TYP][off];
            out[off] = z * hself[off] + (1.f - z) * ht;
        }
    }
}

// ---------------- launch ------------------------------------------------------------
extern "C" void kernel_launch(void* const* d_in, const int* in_sizes, int n_in,
                              void* d_out, int out_size) {
    const float* x_user = (const float*)d_in[0];
    const float* x_news = (const float*)d_in[1];
    const float* h_user = (const float*)d_in[2];
    const float* h_news = (const float*)d_in[3];
    const float* Wl     = (const float*)d_in[4];
    const float* Wr     = (const float*)d_in[5];
    const float* b      = (const float*)d_in[6];
    const int* src_un   = (const int*)d_in[7];
    const int* dst_un   = (const int*)d_in[8];
    const int* src_nu   = (const int*)d_in[9];
    const int* dst_nu   = (const int*)d_in[10];
    float* out = (float*)d_out;
    const int E = in_sizes[7];

    const int nElem = N_NODES * DIM;
    k_zero<<<(nElem + 255) / 256, 256>>>();
    k_repack<<<(2 * 512 * 384 + 2 * 256 * 128 + 2 * 128 + 255) / 256, 256>>>(Wl, Wr, b);
    k_deg<<<(E + 255) / 256, 256>>>(dst_un, dst_nu, E);

    long th = (long)E * 32;
    int sblocks = (int)((th + 255) / 256);
    k_scatter_xh<1><<<sblocks, 256>>>(x_user, h_user, src_un, dst_un, E);
    k_scatter_xh<0><<<sblocks, 256>>>(x_news, h_news, src_nu, dst_nu, E);
    k_norm<0><<<(nElem + 255) / 256, 256>>>();

    dim3 gA((N_NODES + 127) / 128, 3);
    k_gemmA<0><<<gA, 256>>>(x_user, h_user);
    k_gemmA<1><<<gA, 256>>>(x_news, h_news);

    k_scatter_hr<0><<<sblocks, 256>>>(src_nu, dst_nu, E);
    k_scatter_hr<1><<<sblocks, 256>>>(src_un, dst_un, E);
    k_norm<1><<<(nElem + 255) / 256, 256>>>();

    dim3 gB((N_NODES + 127) / 128, 1);
    k_gemmB<0><<<gB, 256>>>(h_user, out);
    k_gemmB<1><<<gB, 256>>>(h_news, out + (size_t)N_NODES * DIM);
}

// round 5
// speedup vs baseline: 1.5817x; 1.5817x over previous
#include <cuda_runtime.h>
#include <cuda_bf16.h>
#include <math.h>
#include <stdint.h>

#define N_NODES 50000
#define DIM     128
#define NTM     391
#define MPAD    (NTM * 128)   // 50048, zero-padded rows

// ---------------- fp32 scratch ---------------------------------------------------
__device__ __align__(16) float g_aggx [2][N_NODES * DIM];
__device__ __align__(16) float g_aggh [2][N_NODES * DIM];
__device__ __align__(16) float g_agghr[2][N_NODES * DIM];
__device__ __align__(16) float g_z    [2][N_NODES * DIM];
__device__ __align__(16) float g_hr   [2][N_NODES * DIM];
__device__ __align__(16) float g_cx   [2][N_NODES * DIM];
__device__ float g_deg[2][N_NODES];
__device__ float g_bias [2][3][DIM];
__device__ float g_bias5[2][DIM];

// ---------------- bf16 hi/lo operands, row-major [MPAD][128] ----------------------
// A operands o: 0=aggx 1=x 2=aggh 3=h ; hl: 0=hi 1=lo
__device__ __align__(16) __nv_bfloat16 g_Abf[2][4][2][(size_t)MPAD * DIM];
// B-pass operands o: 0=agghr 1=hr
__device__ __align__(16) __nv_bfloat16 g_Bbf[2][2][2][(size_t)MPAD * DIM];
// packed weights W^T: [n rows 128][k cols], k ordered (group g, operand o, kk)
__device__ __align__(16) __nv_bfloat16 g_W2A[2][3][128 * 1536];
__device__ __align__(16) __nv_bfloat16 g_W2B[2][128 * 768];

// ---------------- helpers ----------------------------------------------------------
__device__ __forceinline__ uint32_t smem_u32(const void* p) {
    uint32_t a;
    asm("{ .reg .u64 t; cvta.to.shared.u64 t, %1; cvt.u32.u64 %0, t; }" : "=r"(a) : "l"(p));
    return a;
}
__device__ __forceinline__ void ldsm4(uint32_t* r, uint32_t addr) {
    asm volatile("ldmatrix.sync.aligned.m8n8.x4.shared.b16 {%0,%1,%2,%3}, [%4];"
                 : "=r"(r[0]), "=r"(r[1]), "=r"(r[2]), "=r"(r[3]) : "r"(addr));
}
__device__ __forceinline__ void mma16816(float* c, const uint32_t* a, uint32_t b0, uint32_t b1) {
    asm volatile(
        "mma.sync.aligned.m16n8k16.row.col.f32.bf16.bf16.f32 "
        "{%0,%1,%2,%3}, {%4,%5,%6,%7}, {%8,%9}, {%0,%1,%2,%3};"
        : "+f"(c[0]), "+f"(c[1]), "+f"(c[2]), "+f"(c[3])
        : "r"(a[0]), "r"(a[1]), "r"(a[2]), "r"(a[3]), "r"(b0), "r"(b1));
}
__device__ __forceinline__ float sigmoidf_(float v) { return 1.f / (1.f + expf(-v)); }
__device__ __forceinline__ uint32_t packbf(float x, float y) {
    __nv_bfloat162 v = __floats2bfloat162_rn(x, y);
    return *(uint32_t*)&v;
}

// ---------------- zero / degree / scatter (unchanged, proven) ----------------------
__global__ void k_zero() {
    int idx = blockIdx.x * blockDim.x + threadIdx.x;
    if (idx < N_NODES * DIM) {
        g_aggx[0][idx] = 0.f; g_aggx[1][idx] = 0.f;
        g_aggh[0][idx] = 0.f; g_aggh[1][idx] = 0.f;
        g_agghr[0][idx] = 0.f; g_agghr[1][idx] = 0.f;
    }
    if (idx < N_NODES) { g_deg[0][idx] = 0.f; g_deg[1][idx] = 0.f; }
}

__global__ void k_deg(const int* __restrict__ dst_un, const int* __restrict__ dst_nu, int E) {
    int e = blockIdx.x * blockDim.x + threadIdx.x;
    if (e < E) {
        atomicAdd(&g_deg[1][dst_un[e]], 1.f);
        atomicAdd(&g_deg[0][dst_nu[e]], 1.f);
    }
}

template <int TYP>
__global__ void k_scatter_xh(const float* __restrict__ xsrc, const float* __restrict__ hsrc,
                             const int* __restrict__ src, const int* __restrict__ dst, int E) {
    long t = (long)blockIdx.x * blockDim.x + threadIdx.x;
    int e = (int)(t >> 5);
    int lane = (int)(t & 31);
    if (e >= E) return;
    int s = __ldg(src + e);
    int d = __ldg(dst + e);
    float4 vx = ((const float4*)(xsrc + (size_t)s * DIM))[lane];
    float4 vh = ((const float4*)(hsrc + (size_t)s * DIM))[lane];
    atomicAdd(((float4*)(g_aggx[TYP] + (size_t)d * DIM)) + lane, vx);
    atomicAdd(((float4*)(g_aggh[TYP] + (size_t)d * DIM)) + lane, vh);
}

template <int TYP>
__global__ void k_scatter_hr(const int* __restrict__ src, const int* __restrict__ dst, int E) {
    long t = (long)blockIdx.x * blockDim.x + threadIdx.x;
    int e = (int)(t >> 5);
    int lane = (int)(t & 31);
    if (e >= E) return;
    int s = __ldg(src + e);
    int d = __ldg(dst + e);
    const float* f = g_hr[1 - TYP];
    float4 v = ((const float4*)(f + (size_t)s * DIM))[lane];
    atomicAdd(((float4*)(g_agghr[TYP] + (size_t)d * DIM)) + lane, v);
}

// ---------------- bf16 hi/lo conversions -------------------------------------------
__device__ __forceinline__ void conv_store8(const float* v, void* dhi, void* dlo) {
    uint32_t ph[4], pl[4];
#pragma unroll
    for (int i = 0; i < 4; i++) {
        float a = v[2 * i], bq = v[2 * i + 1];
        __nv_bfloat16 h0 = __float2bfloat16(a);
        __nv_bfloat16 h1 = __float2bfloat16(bq);
        __nv_bfloat16 l0 = __float2bfloat16(a - __bfloat162float(h0));
        __nv_bfloat16 l1 = __float2bfloat16(bq - __bfloat162float(h1));
        ph[i] = (uint32_t)__bfloat16_as_ushort(h0) | ((uint32_t)__bfloat16_as_ushort(h1) << 16);
        pl[i] = (uint32_t)__bfloat16_as_ushort(l0) | ((uint32_t)__bfloat16_as_ushort(l1) << 16);
    }
    *(uint4*)dhi = make_uint4(ph[0], ph[1], ph[2], ph[3]);
    *(uint4*)dlo = make_uint4(pl[0], pl[1], pl[2], pl[3]);
}

__global__ void k_conv_xh(const float* __restrict__ xu, const float* __restrict__ hu,
                          const float* __restrict__ xn, const float* __restrict__ hn) {
    int idx = blockIdx.x * blockDim.x + threadIdx.x;
    if (idx >= 2 * 2 * MPAD * 16) return;
    int g = idx & 15;
    int rid = idx >> 4;
    int row = rid % MPAD;
    int rest = rid / MPAD;
    int which = rest & 1;   // 0: x -> o=1, 1: h -> o=3
    int t = rest >> 1;
    float v[8] = {0, 0, 0, 0, 0, 0, 0, 0};
    if (row < N_NODES) {
        const float* src = (t == 0) ? (which ? hu : xu) : (which ? hn : xn);
        const float* p = src + (size_t)row * DIM + g * 8;
        float4 a = ((const float4*)p)[0];
        float4 b4 = ((const float4*)p)[1];
        v[0] = a.x; v[1] = a.y; v[2] = a.z; v[3] = a.w;
        v[4] = b4.x; v[5] = b4.y; v[6] = b4.z; v[7] = b4.w;
    }
    int o = which ? 3 : 1;
    size_t off = (size_t)row * DIM + g * 8;
    conv_store8(v, &g_Abf[t][o][0][off], &g_Abf[t][o][1][off]);
}

__global__ void k_norm_conv() {
    int idx = blockIdx.x * blockDim.x + threadIdx.x;
    if (idx >= 2 * 2 * MPAD * 16) return;
    int g = idx & 15;
    int rid = idx >> 4;
    int row = rid % MPAD;
    int rest = rid / MPAD;
    int which = rest & 1;   // 0: aggx -> o=0, 1: aggh -> o=2
    int t = rest >> 1;
    float v[8] = {0, 0, 0, 0, 0, 0, 0, 0};
    if (row < N_NODES) {
        const float* src = which ? g_aggh[t] : g_aggx[t];
        float inv = 1.f / fmaxf(g_deg[t][row], 1.f);
        const float* p = src + (size_t)row * DIM + g * 8;
        float4 a = ((const float4*)p)[0];
        float4 b4 = ((const float4*)p)[1];
        v[0] = a.x * inv; v[1] = a.y * inv; v[2] = a.z * inv; v[3] = a.w * inv;
        v[4] = b4.x * inv; v[5] = b4.y * inv; v[6] = b4.z * inv; v[7] = b4.w * inv;
    }
    int o = which ? 2 : 0;
    size_t off = (size_t)row * DIM + g * 8;
    conv_store8(v, &g_Abf[t][o][0][off], &g_Abf[t][o][1][off]);
}

__global__ void k_norm_convhr() {
    int idx = blockIdx.x * blockDim.x + threadIdx.x;
    if (idx >= 2 * MPAD * 16) return;
    int g = idx & 15;
    int rid = idx >> 4;
    int row = rid % MPAD;
    int t = rid / MPAD;
    float v[8] = {0, 0, 0, 0, 0, 0, 0, 0};
    if (row < N_NODES) {
        float inv = 1.f / fmaxf(g_deg[t][row], 1.f);
        const float* p = g_agghr[t] + (size_t)row * DIM + g * 8;
        float4 a = ((const float4*)p)[0];
        float4 b4 = ((const float4*)p)[1];
        v[0] = a.x * inv; v[1] = a.y * inv; v[2] = a.z * inv; v[3] = a.w * inv;
        v[4] = b4.x * inv; v[5] = b4.y * inv; v[6] = b4.z * inv; v[7] = b4.w * inv;
    }
    size_t off = (size_t)row * DIM + g * 8;
    conv_store8(v, &g_Bbf[t][0][0][off], &g_Bbf[t][0][1][off]);
}

// ---------------- weight / bias repack ----------------------------------------------
// k ordering: seg s = g*NO + o ; g: 0=(Ahi,Whi) 1=(Ahi,Wlo) 2=(Alo,Whi)
#define W2A_TOT (2 * 3 * 128 * 1536)
#define W2B_TOT (2 * 128 * 768)
__global__ void k_repackW(const float* __restrict__ Wl, const float* __restrict__ Wr) {
    int idx = blockIdx.x * blockDim.x + threadIdx.x;
    if (idx < W2A_TOT) {
        int t = idx / (3 * 128 * 1536);
        int r = idx % (3 * 128 * 1536);
        int ct = r / (128 * 1536);
        int r2 = r % (128 * 1536);
        int n = r2 / 1536;
        int k = r2 % 1536;
        __nv_bfloat16 outv = __float2bfloat16(0.f);
        if (!(ct == 2 && k >= 768)) {
            int s = k >> 7, kk = k & 127;
            int g, o;
            if (ct < 2) { g = s >> 2; o = s & 3; }
            else        { g = s >> 1; o = s & 1; }
            int gate = ct * 2 + ((ct < 2 && o >= 2) ? 1 : 0);
            const float* Wsrc = ((o & 1) == 0) ? Wl : Wr;
            int wi = 1 - t;
            float w = Wsrc[((size_t)(gate * 2 + wi) * 128 + kk) * 128 + n];
            __nv_bfloat16 hi = __float2bfloat16(w);
            outv = (g == 1) ? __float2bfloat16(w - __bfloat162float(hi)) : hi;
        }
        g_W2A[t][ct][n * 1536 + k] = outv;
        return;
    }
    int i2 = idx - W2A_TOT;
    if (i2 < W2B_TOT) {
        int t = i2 / (128 * 768);
        int r2 = i2 % (128 * 768);
        int n = r2 / 768;
        int k = r2 % 768;
        int s = k >> 7, kk = k & 127;
        int g = s >> 1, o = s & 1;
        const float* Wsrc = (o == 0) ? Wl : Wr;
        int wi = 1 - t;
        float w = Wsrc[((size_t)(5 * 2 + wi) * 128 + kk) * 128 + n];
        __nv_bfloat16 hi = __float2bfloat16(w);
        g_W2B[t][n * 768 + k] = (g == 1) ? __float2bfloat16(w - __bfloat162float(hi)) : hi;
    }
}

__global__ void k_repack2(const float* __restrict__ b) {
    int idx = blockIdx.x * blockDim.x + threadIdx.x;
    if (idx >= 2 * 128) return;
    int t = idx / 128, c = idx % 128;
    int wi = 1 - t;
    g_bias[t][0][c] = b[(0 * 2 + wi) * 128 + c] + b[(1 * 2 + wi) * 128 + c];
    g_bias[t][1][c] = b[(2 * 2 + wi) * 128 + c] + b[(3 * 2 + wi) * 128 + c];
    g_bias[t][2][c] = b[(4 * 2 + wi) * 128 + c];
    g_bias5[t][c]   = b[(5 * 2 + wi) * 128 + c];
}

// ---------------- bf16 tensor-core GEMM (mma.sync) -----------------------------------
// BM=128 BN=128 BK=32, 256 threads, 8 warps (2 M x 4 N), warp tile 64x32.
// smem rows padded to 80B (conflict-free ldmatrix).
__device__ __forceinline__ void load_tile(uint32_t sa, uint32_t sw,
                                          const __nv_bfloat16* Ag, const __nv_bfloat16* Wg,
                                          int ldw, int tid) {
#pragma unroll
    for (int i = 0; i < 2; i++) {
        int c = tid * 2 + i;
        int row = c >> 2, q = c & 3;
        uint32_t d = sa + (uint32_t)(row * 80 + q * 16);
        const void* s = Ag + (size_t)row * 128 + q * 8;
        asm volatile("cp.async.cg.shared.global [%0], [%1], 16;" :: "r"(d), "l"(s));
        uint32_t d2 = sw + (uint32_t)(row * 80 + q * 16);
        const void* s2 = Wg + (size_t)row * ldw + q * 8;
        asm volatile("cp.async.cg.shared.global [%0], [%1], 16;" :: "r"(d2), "l"(s2));
    }
    asm volatile("cp.async.commit_group;");
}

template <int PASS>
__global__ void __launch_bounds__(256, 2) k_mma(const float* __restrict__ hu,
                                                const float* __restrict__ hn,
                                                float* __restrict__ out) {
    __shared__ __align__(16) unsigned char sA[2][128 * 80];
    __shared__ __align__(16) unsigned char sW[2][128 * 80];
    const int typ = blockIdx.z, ct = blockIdx.y, tm = blockIdx.x;
    const int tid = threadIdx.x, wid = tid >> 5, lane = tid & 31;
    const int wm = wid & 1, wn = wid >> 1;

    const int NO   = (PASS == 0) ? ((ct < 2) ? 4 : 2) : 2;
    const int NIT  = 3 * NO * 4;
    // W row stride is the ALLOCATED stride (1536 for all of W2A; 768 for W2B),
    // independent of the k-range actually consumed (fix for round-4 bug).
    const int ldw  = (PASS == 0) ? 1536 : 768;
    const __nv_bfloat16* Wrow = (PASS == 0) ? g_W2A[typ][ct] : g_W2B[typ];

    uint32_t sAu[2] = { smem_u32(sA[0]), smem_u32(sA[1]) };
    uint32_t sWu[2] = { smem_u32(sW[0]), smem_u32(sW[1]) };

    float acc[4][4][4];
#pragma unroll
    for (int a = 0; a < 4; a++)
#pragma unroll
        for (int bq = 0; bq < 4; bq++)
#pragma unroll
            for (int cq = 0; cq < 4; cq++) acc[a][bq][cq] = 0.f;

    // segment -> A pointer
    auto asegp = [&](int s) -> const __nv_bfloat16* {
        int g = (NO == 4) ? (s >> 2) : (s >> 1);
        int o = (NO == 4) ? (s & 3) : (s & 1);
        int hl = (g == 2) ? 1 : 0;
        return (PASS == 0) ? &g_Abf[typ][o][hl][0] : &g_Bbf[typ][o][hl][0];
    };

    {
        const __nv_bfloat16* Ag = asegp(0) + (size_t)(tm * 128) * 128;
        load_tile(sAu[0], sWu[0], Ag, Wrow, ldw, tid);
    }

#pragma unroll 1
    for (int kt = 0; kt < NIT; kt++) {
        int bsel = kt & 1;
        if (kt + 1 < NIT) {
            int s = (kt + 1) >> 2, kk = ((kt + 1) & 3) * 32;
            const __nv_bfloat16* Ag = asegp(s) + (size_t)(tm * 128) * 128 + kk;
            const __nv_bfloat16* Wg = Wrow + s * 128 + kk;
            load_tile(sAu[bsel ^ 1], sWu[bsel ^ 1], Ag, Wg, ldw, tid);
            asm volatile("cp.async.wait_group 1;");
        } else {
            asm volatile("cp.async.wait_group 0;");
        }
        __syncthreads();

        uint32_t aB = sAu[bsel] + (uint32_t)((wm * 64) * 80);
        uint32_t bB = sWu[bsel] + (uint32_t)((wn * 32) * 80);
#pragma unroll
        for (int k16 = 0; k16 < 2; k16++) {
            uint32_t afr[4][4], bfr[2][4];
#pragma unroll
            for (int mt = 0; mt < 4; mt++) {
                uint32_t addr = aB + (uint32_t)((mt * 16 + (lane & 15)) * 80 +
                                                k16 * 32 + (lane >> 4) * 16);
                ldsm4(afr[mt], addr);
            }
#pragma unroll
            for (int np = 0; np < 2; np++) {
                uint32_t addr = bB + (uint32_t)((np * 16 + (lane & 7) + ((lane >> 4) * 8)) * 80 +
                                                k16 * 32 + ((lane >> 3) & 1) * 16);
                ldsm4(bfr[np], addr);
            }
#pragma unroll
            for (int mt = 0; mt < 4; mt++)
#pragma unroll
                for (int nt = 0; nt < 4; nt++)
                    mma16816(acc[mt][nt], afr[mt],
                             bfr[nt >> 1][(nt & 1) * 2], bfr[nt >> 1][(nt & 1) * 2 + 1]);
        }
        __syncthreads();
    }

    // ---------------- epilogue ----------------
    const float* hself = typ ? hn : hu;
    int rowW = tm * 128 + wm * 64;
    int colW = wn * 32;
#pragma unroll
    for (int mt = 0; mt < 4; mt++) {
#pragma unroll
        for (int i = 0; i < 2; i++) {
            int row = rowW + mt * 16 + (lane >> 2) + i * 8;
            if (row >= N_NODES) continue;
#pragma unroll
            for (int nt = 0; nt < 4; nt++) {
                int col = colW + nt * 8 + (lane & 3) * 2;
                size_t off = (size_t)row * DIM + col;
                float v0, v1;
                if (PASS == 0) {
                    const float* bias = g_bias[typ][ct];
                    v0 = acc[mt][nt][i * 2 + 0] + bias[col];
                    v1 = acc[mt][nt][i * 2 + 1] + bias[col + 1];
                    if (ct == 0) {
                        *(float2*)&g_z[typ][off] = make_float2(sigmoidf_(v0), sigmoidf_(v1));
                    } else if (ct == 1) {
                        float2 h2 = *(const float2*)&hself[off];
                        float hr0 = h2.x * sigmoidf_(v0);
                        float hr1 = h2.y * sigmoidf_(v1);
                        *(float2*)&g_hr[typ][off] = make_float2(hr0, hr1);
                        __nv_bfloat16 bh0 = __float2bfloat16(hr0);
                        __nv_bfloat16 bh1 = __float2bfloat16(hr1);
                        uint32_t hi = (uint32_t)__bfloat16_as_ushort(bh0) |
                                      ((uint32_t)__bfloat16_as_ushort(bh1) << 16);
                        uint32_t lo = packbf(hr0 - __bfloat162float(bh0),
                                             hr1 - __bfloat162float(bh1));
                        *(uint32_t*)&g_Bbf[typ][1][0][off] = hi;
                        *(uint32_t*)&g_Bbf[typ][1][1][off] = lo;
                    } else {
                        *(float2*)&g_cx[typ][off] = make_float2(v0, v1);
                    }
                } else {
                    const float* bias = g_bias5[typ];
                    v0 = acc[mt][nt][i * 2 + 0] + bias[col];
                    v1 = acc[mt][nt][i * 2 + 1] + bias[col + 1];
                    float2 cx2 = *(const float2*)&g_cx[typ][off];
                    float2 z2  = *(const float2*)&g_z[typ][off];
                    float2 h2  = *(const float2*)&hself[off];
                    float ht0 = tanhf(cx2.x + v0);
                    float ht1 = tanhf(cx2.y + v1);
                    float2 o2;
                    o2.x = z2.x * h2.x + (1.f - z2.x) * ht0;
                    o2.y = z2.y * h2.y + (1.f - z2.y) * ht1;
                    *(float2*)&out[(size_t)typ * N_NODES * DIM + off] = o2;
                }
            }
        }
    }
}

// ---------------- launch ----------------------------------------------------------------
extern "C" void kernel_launch(void* const* d_in, const int* in_sizes, int n_in,
                              void* d_out, int out_size) {
    const float* x_user = (const float*)d_in[0];
    const float* x_news = (const float*)d_in[1];
    const float* h_user = (const float*)d_in[2];
    const float* h_news = (const float*)d_in[3];
    const float* Wl     = (const float*)d_in[4];
    const float* Wr     = (const float*)d_in[5];
    const float* b      = (const float*)d_in[6];
    const int* src_un   = (const int*)d_in[7];
    const int* dst_un   = (const int*)d_in[8];
    const int* src_nu   = (const int*)d_in[9];
    const int* dst_nu   = (const int*)d_in[10];
    float* out = (float*)d_out;
    const int E = in_sizes[7];

    const int nElem = N_NODES * DIM;
    k_zero<<<(nElem + 255) / 256, 256>>>();
    k_repackW<<<(W2A_TOT + W2B_TOT + 255) / 256, 256>>>(Wl, Wr);
    k_repack2<<<1, 256>>>(b);
    k_deg<<<(E + 255) / 256, 256>>>(dst_un, dst_nu, E);
    k_conv_xh<<<(2 * 2 * MPAD * 16 + 255) / 256, 256>>>(x_user, h_user, x_news, h_news);

    long th = (long)E * 32;
    int sblocks = (int)((th + 255) / 256);
    k_scatter_xh<1><<<sblocks, 256>>>(x_user, h_user, src_un, dst_un, E);
    k_scatter_xh<0><<<sblocks, 256>>>(x_news, h_news, src_nu, dst_nu, E);
    k_norm_conv<<<(2 * 2 * MPAD * 16 + 255) / 256, 256>>>();

    dim3 gA(NTM, 3, 2);
    k_mma<0><<<gA, 256>>>(h_user, h_news, out);

    k_scatter_hr<0><<<sblocks, 256>>>(src_nu, dst_nu, E);
    k_scatter_hr<1><<<sblocks, 256>>>(src_un, dst_un, E);
    k_norm_convhr<<<(2 * MPAD * 16 + 255) / 256, 256>>>();

    dim3 gB(NTM, 1, 2);
    k_mma<1><<<gB, 256>>>(h_user, h_news, out);
}

// round 6
// speedup vs baseline: 2.1466x; 1.3571x over previous
#include <cuda_runtime.h>
#include <cuda_bf16.h>
#include <math.h>
#include <stdint.h>

#define N_NODES 50000
#define DIM     128
#define NTM     391
#define MPAD    (NTM * 128)   // 50048, zero-padded rows
#define E_MAX   800000

// ---------------- fp32 scratch ---------------------------------------------------
__device__ __align__(16) float g_z    [2][N_NODES * DIM];
__device__ __align__(16) float g_hr   [2][N_NODES * DIM];
__device__ __align__(16) float g_cx   [2][N_NODES * DIM];
__device__ float g_bias [2][3][DIM];
__device__ float g_bias5[2][DIM];

// ---------------- CSR structures ---------------------------------------------------
__device__ int g_degi[2][N_NODES];
__device__ int g_off [2][N_NODES];
__device__ int g_cur [2][N_NODES];
__device__ int g_srcs[2][E_MAX];

// ---------------- bf16 hi/lo operands, row-major [MPAD][128] ----------------------
// A operands o: 0=aggx 1=x 2=aggh 3=h ; hl: 0=hi 1=lo
__device__ __align__(16) __nv_bfloat16 g_Abf[2][4][2][(size_t)MPAD * DIM];
// B-pass operands o: 0=agghr 1=hr
__device__ __align__(16) __nv_bfloat16 g_Bbf[2][2][2][(size_t)MPAD * DIM];
// packed weights W^T: [n rows 128][k cols]
__device__ __align__(16) __nv_bfloat16 g_W2A[2][3][128 * 1536];
__device__ __align__(16) __nv_bfloat16 g_W2B[2][128 * 768];

// ---------------- helpers ----------------------------------------------------------
__device__ __forceinline__ uint32_t smem_u32(const void* p) {
    uint32_t a;
    asm("{ .reg .u64 t; cvta.to.shared.u64 t, %1; cvt.u32.u64 %0, t; }" : "=r"(a) : "l"(p));
    return a;
}
__device__ __forceinline__ void ldsm4(uint32_t* r, uint32_t addr) {
    asm volatile("ldmatrix.sync.aligned.m8n8.x4.shared.b16 {%0,%1,%2,%3}, [%4];"
                 : "=r"(r[0]), "=r"(r[1]), "=r"(r[2]), "=r"(r[3]) : "r"(addr));
}
__device__ __forceinline__ void mma16816(float* c, const uint32_t* a, uint32_t b0, uint32_t b1) {
    asm volatile(
        "mma.sync.aligned.m16n8k16.row.col.f32.bf16.bf16.f32 "
        "{%0,%1,%2,%3}, {%4,%5,%6,%7}, {%8,%9}, {%0,%1,%2,%3};"
        : "+f"(c[0]), "+f"(c[1]), "+f"(c[2]), "+f"(c[3])
        : "r"(a[0]), "r"(a[1]), "r"(a[2]), "r"(a[3]), "r"(b0), "r"(b1));
}
__device__ __forceinline__ float sigmoidf_(float v) { return 1.f / (1.f + expf(-v)); }
__device__ __forceinline__ uint32_t packbf(float x, float y) {
    __nv_bfloat162 v = __floats2bfloat162_rn(x, y);
    return *(uint32_t*)&v;
}
// 4 floats -> hi uint2 + lo uint2 (bf16 pairs)
__device__ __forceinline__ void hilo_store4(const float* v, void* hip, void* lop) {
    uint32_t h[2], l[2];
#pragma unroll
    for (int i = 0; i < 2; i++) {
        __nv_bfloat16 h0 = __float2bfloat16(v[2 * i]);
        __nv_bfloat16 h1 = __float2bfloat16(v[2 * i + 1]);
        __nv_bfloat16 l0 = __float2bfloat16(v[2 * i] - __bfloat162float(h0));
        __nv_bfloat16 l1 = __float2bfloat16(v[2 * i + 1] - __bfloat162float(h1));
        h[i] = (uint32_t)__bfloat16_as_ushort(h0) | ((uint32_t)__bfloat16_as_ushort(h1) << 16);
        l[i] = (uint32_t)__bfloat16_as_ushort(l0) | ((uint32_t)__bfloat16_as_ushort(l1) << 16);
    }
    *(uint2*)hip = make_uint2(h[0], h[1]);
    *(uint2*)lop = make_uint2(l[0], l[1]);
}

// ---------------- CSR build ---------------------------------------------------------
__global__ void k_zero2() {
    int i = blockIdx.x * blockDim.x + threadIdx.x;
    if (i < N_NODES) {
        g_degi[0][i] = 0; g_degi[1][i] = 0;
        g_cur[0][i] = 0;  g_cur[1][i] = 0;
    }
}

__global__ void k_deg2(const int* __restrict__ dst_un, const int* __restrict__ dst_nu, int E) {
    int e = blockIdx.x * blockDim.x + threadIdx.x;
    if (e < E) {
        atomicAdd(&g_degi[1][dst_un[e]], 1);
        atomicAdd(&g_degi[0][dst_nu[e]], 1);
    }
}

// one block per type; exclusive scan of degi -> off
__global__ void __launch_bounds__(1024) k_scan() {
    const int t = blockIdx.x;
    __shared__ int wsum[32];
    __shared__ int carry;
    if (threadIdx.x == 0) carry = 0;
    __syncthreads();
    int lane = threadIdx.x & 31, wid = threadIdx.x >> 5;
    for (int base = 0; base < N_NODES; base += 1024) {
        int i = base + threadIdx.x;
        int v = (i < N_NODES) ? g_degi[t][i] : 0;
        int s = v;
#pragma unroll
        for (int o = 1; o < 32; o <<= 1) {
            int u = __shfl_up_sync(0xFFFFFFFFu, s, o);
            if (lane >= o) s += u;
        }
        if (lane == 31) wsum[wid] = s;
        __syncthreads();
        if (wid == 0) {
            int ws = wsum[lane];
#pragma unroll
            for (int o = 1; o < 32; o <<= 1) {
                int u = __shfl_up_sync(0xFFFFFFFFu, ws, o);
                if (lane >= o) ws += u;
            }
            wsum[lane] = ws;
        }
        __syncthreads();
        int excl = carry + (wid > 0 ? wsum[wid - 1] : 0) + s - v;
        if (i < N_NODES) g_off[t][i] = excl;
        int total = wsum[31];
        __syncthreads();
        if (threadIdx.x == 0) carry += total;
        __syncthreads();
    }
}

__global__ void k_fill(const int* __restrict__ src_un, const int* __restrict__ dst_un,
                       const int* __restrict__ src_nu, const int* __restrict__ dst_nu, int E) {
    int e = blockIdx.x * blockDim.x + threadIdx.x;
    if (e >= E) return;
    int d1 = dst_un[e];
    int p1 = atomicAdd(&g_cur[1][d1], 1);
    g_srcs[1][g_off[1][d1] + p1] = src_un[e];
    int d0 = dst_nu[e];
    int p0 = atomicAdd(&g_cur[0][d0], 1);
    g_srcs[0][g_off[0][d0] + p0] = src_nu[e];
}

// ---------------- gather aggregation: warp per dst row -------------------------------
// gathers x,h rows of source nodes; mean; fused bf16 hi/lo store into g_Abf o=0 (aggx), o=2 (aggh)
template <int TYP>
__global__ void k_agg_xh(const float* __restrict__ xs, const float* __restrict__ hs) {
    int w = (blockIdx.x * blockDim.x + threadIdx.x) >> 5;
    int lane = threadIdx.x & 31;
    if (w >= MPAD) return;
    int n = 0, beg = 0;
    if (w < N_NODES) { n = g_degi[TYP][w]; beg = g_off[TYP][w]; }
    const int* sp = &g_srcs[TYP][beg];
    float4 ax = make_float4(0.f, 0.f, 0.f, 0.f);
    float4 ah = make_float4(0.f, 0.f, 0.f, 0.f);
    int j = 0;
    for (; j + 4 <= n; j += 4) {
        int s0 = __ldg(sp + j), s1 = __ldg(sp + j + 1);
        int s2 = __ldg(sp + j + 2), s3 = __ldg(sp + j + 3);
        float4 x0 = ((const float4*)(xs + (size_t)s0 * DIM))[lane];
        float4 x1 = ((const float4*)(xs + (size_t)s1 * DIM))[lane];
        float4 x2 = ((const float4*)(xs + (size_t)s2 * DIM))[lane];
        float4 x3 = ((const float4*)(xs + (size_t)s3 * DIM))[lane];
        float4 h0 = ((const float4*)(hs + (size_t)s0 * DIM))[lane];
        float4 h1 = ((const float4*)(hs + (size_t)s1 * DIM))[lane];
        float4 h2 = ((const float4*)(hs + (size_t)s2 * DIM))[lane];
        float4 h3 = ((const float4*)(hs + (size_t)s3 * DIM))[lane];
        ax.x += x0.x + x1.x + x2.x + x3.x;
        ax.y += x0.y + x1.y + x2.y + x3.y;
        ax.z += x0.z + x1.z + x2.z + x3.z;
        ax.w += x0.w + x1.w + x2.w + x3.w;
        ah.x += h0.x + h1.x + h2.x + h3.x;
        ah.y += h0.y + h1.y + h2.y + h3.y;
        ah.z += h0.z + h1.z + h2.z + h3.z;
        ah.w += h0.w + h1.w + h2.w + h3.w;
    }
    for (; j < n; j++) {
        int s = __ldg(sp + j);
        float4 x0 = ((const float4*)(xs + (size_t)s * DIM))[lane];
        float4 h0 = ((const float4*)(hs + (size_t)s * DIM))[lane];
        ax.x += x0.x; ax.y += x0.y; ax.z += x0.z; ax.w += x0.w;
        ah.x += h0.x; ah.y += h0.y; ah.z += h0.z; ah.w += h0.w;
    }
    float inv = 1.f / (float)max(n, 1);
    float vx[4] = {ax.x * inv, ax.y * inv, ax.z * inv, ax.w * inv};
    float vh[4] = {ah.x * inv, ah.y * inv, ah.z * inv, ah.w * inv};
    size_t off = (size_t)w * DIM + lane * 4;
    hilo_store4(vx, &g_Abf[TYP][0][0][off], &g_Abf[TYP][0][1][off]);
    hilo_store4(vh, &g_Abf[TYP][2][0][off], &g_Abf[TYP][2][1][off]);
}

// gathers h*r (fp32) of the other type; mean; fused hi/lo store into g_Bbf o=0 (agghr)
template <int TYP>
__global__ void k_agg_hr() {
    int w = (blockIdx.x * blockDim.x + threadIdx.x) >> 5;
    int lane = threadIdx.x & 31;
    if (w >= MPAD) return;
    int n = 0, beg = 0;
    if (w < N_NODES) { n = g_degi[TYP][w]; beg = g_off[TYP][w]; }
    const int* sp = &g_srcs[TYP][beg];
    const float* fs = g_hr[1 - TYP];
    float4 a = make_float4(0.f, 0.f, 0.f, 0.f);
    int j = 0;
    for (; j + 4 <= n; j += 4) {
        int s0 = __ldg(sp + j), s1 = __ldg(sp + j + 1);
        int s2 = __ldg(sp + j + 2), s3 = __ldg(sp + j + 3);
        float4 v0 = ((const float4*)(fs + (size_t)s0 * DIM))[lane];
        float4 v1 = ((const float4*)(fs + (size_t)s1 * DIM))[lane];
        float4 v2 = ((const float4*)(fs + (size_t)s2 * DIM))[lane];
        float4 v3 = ((const float4*)(fs + (size_t)s3 * DIM))[lane];
        a.x += v0.x + v1.x + v2.x + v3.x;
        a.y += v0.y + v1.y + v2.y + v3.y;
        a.z += v0.z + v1.z + v2.z + v3.z;
        a.w += v0.w + v1.w + v2.w + v3.w;
    }
    for (; j < n; j++) {
        int s = __ldg(sp + j);
        float4 v0 = ((const float4*)(fs + (size_t)s * DIM))[lane];
        a.x += v0.x; a.y += v0.y; a.z += v0.z; a.w += v0.w;
    }
    float inv = 1.f / (float)max(n, 1);
    float v[4] = {a.x * inv, a.y * inv, a.z * inv, a.w * inv};
    size_t off = (size_t)w * DIM + lane * 4;
    hilo_store4(v, &g_Bbf[TYP][0][0][off], &g_Bbf[TYP][0][1][off]);
}

// ---------------- x/h -> bf16 hi/lo (GEMM self operands) ------------------------------
__device__ __forceinline__ void conv_store8(const float* v, void* dhi, void* dlo) {
    uint32_t ph[4], pl[4];
#pragma unroll
    for (int i = 0; i < 4; i++) {
        float a = v[2 * i], bq = v[2 * i + 1];
        __nv_bfloat16 h0 = __float2bfloat16(a);
        __nv_bfloat16 h1 = __float2bfloat16(bq);
        __nv_bfloat16 l0 = __float2bfloat16(a - __bfloat162float(h0));
        __nv_bfloat16 l1 = __float2bfloat16(bq - __bfloat162float(h1));
        ph[i] = (uint32_t)__bfloat16_as_ushort(h0) | ((uint32_t)__bfloat16_as_ushort(h1) << 16);
        pl[i] = (uint32_t)__bfloat16_as_ushort(l0) | ((uint32_t)__bfloat16_as_ushort(l1) << 16);
    }
    *(uint4*)dhi = make_uint4(ph[0], ph[1], ph[2], ph[3]);
    *(uint4*)dlo = make_uint4(pl[0], pl[1], pl[2], pl[3]);
}

__global__ void k_conv_xh(const float* __restrict__ xu, const float* __restrict__ hu,
                          const float* __restrict__ xn, const float* __restrict__ hn) {
    int idx = blockIdx.x * blockDim.x + threadIdx.x;
    if (idx >= 2 * 2 * MPAD * 16) return;
    int g = idx & 15;
    int rid = idx >> 4;
    int row = rid % MPAD;
    int rest = rid / MPAD;
    int which = rest & 1;   // 0: x -> o=1, 1: h -> o=3
    int t = rest >> 1;
    float v[8] = {0, 0, 0, 0, 0, 0, 0, 0};
    if (row < N_NODES) {
        const float* src = (t == 0) ? (which ? hu : xu) : (which ? hn : xn);
        const float* p = src + (size_t)row * DIM + g * 8;
        float4 a = ((const float4*)p)[0];
        float4 b4 = ((const float4*)p)[1];
        v[0] = a.x; v[1] = a.y; v[2] = a.z; v[3] = a.w;
        v[4] = b4.x; v[5] = b4.y; v[6] = b4.z; v[7] = b4.w;
    }
    int o = which ? 3 : 1;
    size_t off = (size_t)row * DIM + g * 8;
    conv_store8(v, &g_Abf[t][o][0][off], &g_Abf[t][o][1][off]);
}

// ---------------- weight / bias repack ----------------------------------------------
#define W2A_TOT (2 * 3 * 128 * 1536)
#define W2B_TOT (2 * 128 * 768)
__global__ void k_repackW(const float* __restrict__ Wl, const float* __restrict__ Wr) {
    int idx = blockIdx.x * blockDim.x + threadIdx.x;
    if (idx < W2A_TOT) {
        int t = idx / (3 * 128 * 1536);
        int r = idx % (3 * 128 * 1536);
        int ct = r / (128 * 1536);
        int r2 = r % (128 * 1536);
        int n = r2 / 1536;
        int k = r2 % 1536;
        __nv_bfloat16 outv = __float2bfloat16(0.f);
        if (!(ct == 2 && k >= 768)) {
            int s = k >> 7, kk = k & 127;
            int g, o;
            if (ct < 2) { g = s >> 2; o = s & 3; }
            else        { g = s >> 1; o = s & 1; }
            int gate = ct * 2 + ((ct < 2 && o >= 2) ? 1 : 0);
            const float* Wsrc = ((o & 1) == 0) ? Wl : Wr;
            int wi = 1 - t;
            float w = Wsrc[((size_t)(gate * 2 + wi) * 128 + kk) * 128 + n];
            __nv_bfloat16 hi = __float2bfloat16(w);
            outv = (g == 1) ? __float2bfloat16(w - __bfloat162float(hi)) : hi;
        }
        g_W2A[t][ct][n * 1536 + k] = outv;
        return;
    }
    int i2 = idx - W2A_TOT;
    if (i2 < W2B_TOT) {
        int t = i2 / (128 * 768);
        int r2 = i2 % (128 * 768);
        int n = r2 / 768;
        int k = r2 % 768;
        int s = k >> 7, kk = k & 127;
        int g = s >> 1, o = s & 1;
        const float* Wsrc = (o == 0) ? Wl : Wr;
        int wi = 1 - t;
        float w = Wsrc[((size_t)(5 * 2 + wi) * 128 + kk) * 128 + n];
        __nv_bfloat16 hi = __float2bfloat16(w);
        g_W2B[t][n * 768 + k] = (g == 1) ? __float2bfloat16(w - __bfloat162float(hi)) : hi;
    }
}

__global__ void k_repack2(const float* __restrict__ b) {
    int idx = blockIdx.x * blockDim.x + threadIdx.x;
    if (idx >= 2 * 128) return;
    int t = idx / 128, c = idx % 128;
    int wi = 1 - t;
    g_bias[t][0][c] = b[(0 * 2 + wi) * 128 + c] + b[(1 * 2 + wi) * 128 + c];
    g_bias[t][1][c] = b[(2 * 2 + wi) * 128 + c] + b[(3 * 2 + wi) * 128 + c];
    g_bias[t][2][c] = b[(4 * 2 + wi) * 128 + c];
    g_bias5[t][c]   = b[(5 * 2 + wi) * 128 + c];
}

// ---------------- bf16 tensor-core GEMM (mma.sync) -----------------------------------
__device__ __forceinline__ void load_tile(uint32_t sa, uint32_t sw,
                                          const __nv_bfloat16* Ag, const __nv_bfloat16* Wg,
                                          int ldw, int tid) {
#pragma unroll
    for (int i = 0; i < 2; i++) {
        int c = tid * 2 + i;
        int row = c >> 2, q = c & 3;
        uint32_t d = sa + (uint32_t)(row * 80 + q * 16);
        const void* s = Ag + (size_t)row * 128 + q * 8;
        asm volatile("cp.async.cg.shared.global [%0], [%1], 16;" :: "r"(d), "l"(s));
        uint32_t d2 = sw + (uint32_t)(row * 80 + q * 16);
        const void* s2 = Wg + (size_t)row * ldw + q * 8;
        asm volatile("cp.async.cg.shared.global [%0], [%1], 16;" :: "r"(d2), "l"(s2));
    }
    asm volatile("cp.async.commit_group;");
}

template <int PASS>
__global__ void __launch_bounds__(256, 2) k_mma(const float* __restrict__ hu,
                                                const float* __restrict__ hn,
                                                float* __restrict__ out) {
    __shared__ __align__(16) unsigned char sA[2][128 * 80];
    __shared__ __align__(16) unsigned char sW[2][128 * 80];
    const int typ = blockIdx.z, ct = blockIdx.y, tm = blockIdx.x;
    const int tid = threadIdx.x, wid = tid >> 5, lane = tid & 31;
    const int wm = wid & 1, wn = wid >> 1;

    const int NO   = (PASS == 0) ? ((ct < 2) ? 4 : 2) : 2;
    const int NIT  = 3 * NO * 4;
    const int ldw  = (PASS == 0) ? 1536 : 768;
    const __nv_bfloat16* Wrow = (PASS == 0) ? g_W2A[typ][ct] : g_W2B[typ];

    uint32_t sAu[2] = { smem_u32(sA[0]), smem_u32(sA[1]) };
    uint32_t sWu[2] = { smem_u32(sW[0]), smem_u32(sW[1]) };

    float acc[4][4][4];
#pragma unroll
    for (int a = 0; a < 4; a++)
#pragma unroll
        for (int bq = 0; bq < 4; bq++)
#pragma unroll
            for (int cq = 0; cq < 4; cq++) acc[a][bq][cq] = 0.f;

    auto asegp = [&](int s) -> const __nv_bfloat16* {
        int g = (NO == 4) ? (s >> 2) : (s >> 1);
        int o = (NO == 4) ? (s & 3) : (s & 1);
        int hl = (g == 2) ? 1 : 0;
        return (PASS == 0) ? &g_Abf[typ][o][hl][0] : &g_Bbf[typ][o][hl][0];
    };

    {
        const __nv_bfloat16* Ag = asegp(0) + (size_t)(tm * 128) * 128;
        load_tile(sAu[0], sWu[0], Ag, Wrow, ldw, tid);
    }

#pragma unroll 1
    for (int kt = 0; kt < NIT; kt++) {
        int bsel = kt & 1;
        if (kt + 1 < NIT) {
            int s = (kt + 1) >> 2, kk = ((kt + 1) & 3) * 32;
            const __nv_bfloat16* Ag = asegp(s) + (size_t)(tm * 128) * 128 + kk;
            const __nv_bfloat16* Wg = Wrow + s * 128 + kk;
            load_tile(sAu[bsel ^ 1], sWu[bsel ^ 1], Ag, Wg, ldw, tid);
            asm volatile("cp.async.wait_group 1;");
        } else {
            asm volatile("cp.async.wait_group 0;");
        }
        __syncthreads();

        uint32_t aB = sAu[bsel] + (uint32_t)((wm * 64) * 80);
        uint32_t bB = sWu[bsel] + (uint32_t)((wn * 32) * 80);
#pragma unroll
        for (int k16 = 0; k16 < 2; k16++) {
            uint32_t afr[4][4], bfr[2][4];
#pragma unroll
            for (int mt = 0; mt < 4; mt++) {
                uint32_t addr = aB + (uint32_t)((mt * 16 + (lane & 15)) * 80 +
                                                k16 * 32 + (lane >> 4) * 16);
                ldsm4(afr[mt], addr);
            }
#pragma unroll
            for (int np = 0; np < 2; np++) {
                uint32_t addr = bB + (uint32_t)((np * 16 + (lane & 7) + ((lane >> 4) * 8)) * 80 +
                                                k16 * 32 + ((lane >> 3) & 1) * 16);
                ldsm4(bfr[np], addr);
            }
#pragma unroll
            for (int mt = 0; mt < 4; mt++)
#pragma unroll
                for (int nt = 0; nt < 4; nt++)
                    mma16816(acc[mt][nt], afr[mt],
                             bfr[nt >> 1][(nt & 1) * 2], bfr[nt >> 1][(nt & 1) * 2 + 1]);
        }
        __syncthreads();
    }

    // ---------------- epilogue ----------------
    const float* hself = typ ? hn : hu;
    int rowW = tm * 128 + wm * 64;
    int colW = wn * 32;
#pragma unroll
    for (int mt = 0; mt < 4; mt++) {
#pragma unroll
        for (int i = 0; i < 2; i++) {
            int row = rowW + mt * 16 + (lane >> 2) + i * 8;
            if (row >= N_NODES) continue;
#pragma unroll
            for (int nt = 0; nt < 4; nt++) {
                int col = colW + nt * 8 + (lane & 3) * 2;
                size_t off = (size_t)row * DIM + col;
                float v0, v1;
                if (PASS == 0) {
                    const float* bias = g_bias[typ][ct];
                    v0 = acc[mt][nt][i * 2 + 0] + bias[col];
                    v1 = acc[mt][nt][i * 2 + 1] + bias[col + 1];
                    if (ct == 0) {
                        *(float2*)&g_z[typ][off] = make_float2(sigmoidf_(v0), sigmoidf_(v1));
                    } else if (ct == 1) {
                        float2 h2 = *(const float2*)&hself[off];
                        float hr0 = h2.x * sigmoidf_(v0);
                        float hr1 = h2.y * sigmoidf_(v1);
                        *(float2*)&g_hr[typ][off] = make_float2(hr0, hr1);
                        __nv_bfloat16 bh0 = __float2bfloat16(hr0);
                        __nv_bfloat16 bh1 = __float2bfloat16(hr1);
                        uint32_t hi = (uint32_t)__bfloat16_as_ushort(bh0) |
                                      ((uint32_t)__bfloat16_as_ushort(bh1) << 16);
                        uint32_t lo = packbf(hr0 - __bfloat162float(bh0),
                                             hr1 - __bfloat162float(bh1));
                        *(uint32_t*)&g_Bbf[typ][1][0][off] = hi;
                        *(uint32_t*)&g_Bbf[typ][1][1][off] = lo;
                    } else {
                        *(float2*)&g_cx[typ][off] = make_float2(v0, v1);
                    }
                } else {
                    const float* bias = g_bias5[typ];
                    v0 = acc[mt][nt][i * 2 + 0] + bias[col];
                    v1 = acc[mt][nt][i * 2 + 1] + bias[col + 1];
                    float2 cx2 = *(const float2*)&g_cx[typ][off];
                    float2 z2  = *(const float2*)&g_z[typ][off];
                    float2 h2  = *(const float2*)&hself[off];
                    float ht0 = tanhf(cx2.x + v0);
                    float ht1 = tanhf(cx2.y + v1);
                    float2 o2;
                    o2.x = z2.x * h2.x + (1.f - z2.x) * ht0;
                    o2.y = z2.y * h2.y + (1.f - z2.y) * ht1;
                    *(float2*)&out[(size_t)typ * N_NODES * DIM + off] = o2;
                }
            }
        }
    }
}

// ---------------- launch ----------------------------------------------------------------
extern "C" void kernel_launch(void* const* d_in, const int* in_sizes, int n_in,
                              void* d_out, int out_size) {
    const float* x_user = (const float*)d_in[0];
    const float* x_news = (const float*)d_in[1];
    const float* h_user = (const float*)d_in[2];
    const float* h_news = (const float*)d_in[3];
    const float* Wl     = (const float*)d_in[4];
    const float* Wr     = (const float*)d_in[5];
    const float* b      = (const float*)d_in[6];
    const int* src_un   = (const int*)d_in[7];
    const int* dst_un   = (const int*)d_in[8];
    const int* src_nu   = (const int*)d_in[9];
    const int* dst_nu   = (const int*)d_in[10];
    float* out = (float*)d_out;
    const int E = in_sizes[7];

    // CSR build
    k_zero2<<<(N_NODES + 255) / 256, 256>>>();
    k_deg2<<<(E + 255) / 256, 256>>>(dst_un, dst_nu, E);
    k_scan<<<2, 1024>>>();
    k_fill<<<(E + 255) / 256, 256>>>(src_un, dst_un, src_nu, dst_nu, E);

    // weight/bias prep + self-feature conversion (independent)
    k_repackW<<<(W2A_TOT + W2B_TOT + 255) / 256, 256>>>(Wl, Wr);
    k_repack2<<<1, 256>>>(b);
    k_conv_xh<<<(2 * 2 * MPAD * 16 + 255) / 256, 256>>>(x_user, h_user, x_news, h_news);

    // aggregation (gather, fused mean + bf16 hi/lo)
    int ablocks = (MPAD * 32 + 255) / 256;
    k_agg_xh<0><<<ablocks, 256>>>(x_news, h_news);   // user dst <- news sources
    k_agg_xh<1><<<ablocks, 256>>>(x_user, h_user);   // news dst <- user sources

    dim3 gA(NTM, 3, 2);
    k_mma<0><<<gA, 256>>>(h_user, h_news, out);

    k_agg_hr<0><<<ablocks, 256>>>();
    k_agg_hr<1><<<ablocks, 256>>>();

    dim3 gB(NTM, 1, 2);
    k_mma<1><<<gB, 256>>>(h_user, h_news, out);
}

// round 7
// speedup vs baseline: 3.4042x; 1.5858x over previous
#include <cuda_runtime.h>
#include <cuda_fp16.h>
#include <math.h>
#include <stdint.h>

#define N_NODES 50000
#define DIM     128
#define NTM     391
#define MPAD    (NTM * 128)   // 50048, zero-padded rows
#define E_MAX   800000

// ---------------- fp32 scratch ---------------------------------------------------
__device__ __align__(16) float g_z    [2][N_NODES * DIM];
__device__ __align__(16) float g_hr   [2][N_NODES * DIM];
__device__ __align__(16) float g_cx   [2][N_NODES * DIM];
__device__ float g_bias [2][3][DIM];
__device__ float g_bias5[2][DIM];

// ---------------- CSR structures ---------------------------------------------------
__device__ int g_degi[2][N_NODES];
__device__ int g_off [2][N_NODES];
__device__ int g_cur [2][N_NODES];
__device__ int g_srcs[2][E_MAX];

// ---------------- fp16 operands, row-major [MPAD][128] ------------------------------
// A operands o: 0=aggx 1=x 2=aggh 3=h
__device__ __align__(16) __half g_Abf[2][4][(size_t)MPAD * DIM];
// B-pass operands o: 0=agghr 1=hr
__device__ __align__(16) __half g_Bbf[2][2][(size_t)MPAD * DIM];
// packed weights W^T: [n rows 128][k cols]; pass A K=512 (ct=2 uses first 256), pass B K=256
__device__ __align__(16) __half g_W2A[2][3][128 * 512];
__device__ __align__(16) __half g_W2B[2][128 * 256];

// ---------------- helpers ----------------------------------------------------------
__device__ __forceinline__ uint32_t smem_u32(const void* p) {
    uint32_t a;
    asm("{ .reg .u64 t; cvta.to.shared.u64 t, %1; cvt.u32.u64 %0, t; }" : "=r"(a) : "l"(p));
    return a;
}
__device__ __forceinline__ void ldsm4(uint32_t* r, uint32_t addr) {
    asm volatile("ldmatrix.sync.aligned.m8n8.x4.shared.b16 {%0,%1,%2,%3}, [%4];"
                 : "=r"(r[0]), "=r"(r[1]), "=r"(r[2]), "=r"(r[3]) : "r"(addr));
}
__device__ __forceinline__ void mma16816(float* c, const uint32_t* a, uint32_t b0, uint32_t b1) {
    asm volatile(
        "mma.sync.aligned.m16n8k16.row.col.f32.f16.f16.f32 "
        "{%0,%1,%2,%3}, {%4,%5,%6,%7}, {%8,%9}, {%0,%1,%2,%3};"
        : "+f"(c[0]), "+f"(c[1]), "+f"(c[2]), "+f"(c[3])
        : "r"(a[0]), "r"(a[1]), "r"(a[2]), "r"(a[3]), "r"(b0), "r"(b1));
}
__device__ __forceinline__ float sigmoidf_(float v) { return 1.f / (1.f + expf(-v)); }
__device__ __forceinline__ uint32_t packh2(float x, float y) {
    __half2 v = __floats2half2_rn(x, y);
    return *(uint32_t*)&v;
}
// 4 floats -> 4 halves (8 bytes)
__device__ __forceinline__ void h_store4(const float* v, void* dp) {
    *(uint2*)dp = make_uint2(packh2(v[0], v[1]), packh2(v[2], v[3]));
}

// ---------------- CSR build ---------------------------------------------------------
__global__ void k_zero2() {
    int i = blockIdx.x * blockDim.x + threadIdx.x;
    if (i < N_NODES) {
        g_degi[0][i] = 0; g_degi[1][i] = 0;
        g_cur[0][i] = 0;  g_cur[1][i] = 0;
    }
}

__global__ void k_deg2(const int* __restrict__ dst_un, const int* __restrict__ dst_nu, int E) {
    int e = blockIdx.x * blockDim.x + threadIdx.x;
    if (e < E) {
        atomicAdd(&g_degi[1][dst_un[e]], 1);
        atomicAdd(&g_degi[0][dst_nu[e]], 1);
    }
}

// one block per type; exclusive scan of degi -> off
__global__ void __launch_bounds__(1024) k_scan() {
    const int t = blockIdx.x;
    __shared__ int wsum[32];
    __shared__ int carry;
    if (threadIdx.x == 0) carry = 0;
    __syncthreads();
    int lane = threadIdx.x & 31, wid = threadIdx.x >> 5;
    for (int base = 0; base < N_NODES; base += 1024) {
        int i = base + threadIdx.x;
        int v = (i < N_NODES) ? g_degi[t][i] : 0;
        int s = v;
#pragma unroll
        for (int o = 1; o < 32; o <<= 1) {
            int u = __shfl_up_sync(0xFFFFFFFFu, s, o);
            if (lane >= o) s += u;
        }
        if (lane == 31) wsum[wid] = s;
        __syncthreads();
        if (wid == 0) {
            int ws = wsum[lane];
#pragma unroll
            for (int o = 1; o < 32; o <<= 1) {
                int u = __shfl_up_sync(0xFFFFFFFFu, ws, o);
                if (lane >= o) ws += u;
            }
            wsum[lane] = ws;
        }
        __syncthreads();
        int excl = carry + (wid > 0 ? wsum[wid - 1] : 0) + s - v;
        if (i < N_NODES) g_off[t][i] = excl;
        int total = wsum[31];
        __syncthreads();
        if (threadIdx.x == 0) carry += total;
        __syncthreads();
    }
}

__global__ void k_fill(const int* __restrict__ src_un, const int* __restrict__ dst_un,
                       const int* __restrict__ src_nu, const int* __restrict__ dst_nu, int E) {
    int e = blockIdx.x * blockDim.x + threadIdx.x;
    if (e >= E) return;
    int d1 = dst_un[e];
    int p1 = atomicAdd(&g_cur[1][d1], 1);
    g_srcs[1][g_off[1][d1] + p1] = src_un[e];
    int d0 = dst_nu[e];
    int p0 = atomicAdd(&g_cur[0][d0], 1);
    g_srcs[0][g_off[0][d0] + p0] = src_nu[e];
}

// ---------------- gather aggregation: warp per dst row -------------------------------
template <int TYP>
__global__ void k_agg_xh(const float* __restrict__ xs, const float* __restrict__ hs) {
    int w = (blockIdx.x * blockDim.x + threadIdx.x) >> 5;
    int lane = threadIdx.x & 31;
    if (w >= MPAD) return;
    int n = 0, beg = 0;
    if (w < N_NODES) { n = g_degi[TYP][w]; beg = g_off[TYP][w]; }
    const int* sp = &g_srcs[TYP][beg];
    float4 ax = make_float4(0.f, 0.f, 0.f, 0.f);
    float4 ah = make_float4(0.f, 0.f, 0.f, 0.f);
    int j = 0;
    for (; j + 4 <= n; j += 4) {
        int s0 = __ldg(sp + j), s1 = __ldg(sp + j + 1);
        int s2 = __ldg(sp + j + 2), s3 = __ldg(sp + j + 3);
        float4 x0 = ((const float4*)(xs + (size_t)s0 * DIM))[lane];
        float4 x1 = ((const float4*)(xs + (size_t)s1 * DIM))[lane];
        float4 x2 = ((const float4*)(xs + (size_t)s2 * DIM))[lane];
        float4 x3 = ((const float4*)(xs + (size_t)s3 * DIM))[lane];
        float4 h0 = ((const float4*)(hs + (size_t)s0 * DIM))[lane];
        float4 h1 = ((const float4*)(hs + (size_t)s1 * DIM))[lane];
        float4 h2 = ((const float4*)(hs + (size_t)s2 * DIM))[lane];
        float4 h3 = ((const float4*)(hs + (size_t)s3 * DIM))[lane];
        ax.x += x0.x + x1.x + x2.x + x3.x;
        ax.y += x0.y + x1.y + x2.y + x3.y;
        ax.z += x0.z + x1.z + x2.z + x3.z;
        ax.w += x0.w + x1.w + x2.w + x3.w;
        ah.x += h0.x + h1.x + h2.x + h3.x;
        ah.y += h0.y + h1.y + h2.y + h3.y;
        ah.z += h0.z + h1.z + h2.z + h3.z;
        ah.w += h0.w + h1.w + h2.w + h3.w;
    }
    for (; j < n; j++) {
        int s = __ldg(sp + j);
        float4 x0 = ((const float4*)(xs + (size_t)s * DIM))[lane];
        float4 h0 = ((const float4*)(hs + (size_t)s * DIM))[lane];
        ax.x += x0.x; ax.y += x0.y; ax.z += x0.z; ax.w += x0.w;
        ah.x += h0.x; ah.y += h0.y; ah.z += h0.z; ah.w += h0.w;
    }
    float inv = 1.f / (float)max(n, 1);
    float vx[4] = {ax.x * inv, ax.y * inv, ax.z * inv, ax.w * inv};
    float vh[4] = {ah.x * inv, ah.y * inv, ah.z * inv, ah.w * inv};
    size_t off = (size_t)w * DIM + lane * 4;
    h_store4(vx, &g_Abf[TYP][0][off]);
    h_store4(vh, &g_Abf[TYP][2][off]);
}

template <int TYP>
__global__ void k_agg_hr() {
    int w = (blockIdx.x * blockDim.x + threadIdx.x) >> 5;
    int lane = threadIdx.x & 31;
    if (w >= MPAD) return;
    int n = 0, beg = 0;
    if (w < N_NODES) { n = g_degi[TYP][w]; beg = g_off[TYP][w]; }
    const int* sp = &g_srcs[TYP][beg];
    const float* fs = g_hr[1 - TYP];
    float4 a = make_float4(0.f, 0.f, 0.f, 0.f);
    int j = 0;
    for (; j + 4 <= n; j += 4) {
        int s0 = __ldg(sp + j), s1 = __ldg(sp + j + 1);
        int s2 = __ldg(sp + j + 2), s3 = __ldg(sp + j + 3);
        float4 v0 = ((const float4*)(fs + (size_t)s0 * DIM))[lane];
        float4 v1 = ((const float4*)(fs + (size_t)s1 * DIM))[lane];
        float4 v2 = ((const float4*)(fs + (size_t)s2 * DIM))[lane];
        float4 v3 = ((const float4*)(fs + (size_t)s3 * DIM))[lane];
        a.x += v0.x + v1.x + v2.x + v3.x;
        a.y += v0.y + v1.y + v2.y + v3.y;
        a.z += v0.z + v1.z + v2.z + v3.z;
        a.w += v0.w + v1.w + v2.w + v3.w;
    }
    for (; j < n; j++) {
        int s = __ldg(sp + j);
        float4 v0 = ((const float4*)(fs + (size_t)s * DIM))[lane];
        a.x += v0.x; a.y += v0.y; a.z += v0.z; a.w += v0.w;
    }
    float inv = 1.f / (float)max(n, 1);
    float v[4] = {a.x * inv, a.y * inv, a.z * inv, a.w * inv};
    size_t off = (size_t)w * DIM + lane * 4;
    h_store4(v, &g_Bbf[TYP][0][off]);
}

// ---------------- x/h -> fp16 (GEMM self operands) ------------------------------------
__global__ void k_conv_xh(const float* __restrict__ xu, const float* __restrict__ hu,
                          const float* __restrict__ xn, const float* __restrict__ hn) {
    int idx = blockIdx.x * blockDim.x + threadIdx.x;
    if (idx >= 2 * 2 * MPAD * 16) return;
    int g = idx & 15;
    int rid = idx >> 4;
    int row = rid % MPAD;
    int rest = rid / MPAD;
    int which = rest & 1;   // 0: x -> o=1, 1: h -> o=3
    int t = rest >> 1;
    float v[8] = {0, 0, 0, 0, 0, 0, 0, 0};
    if (row < N_NODES) {
        const float* src = (t == 0) ? (which ? hu : xu) : (which ? hn : xn);
        const float* p = src + (size_t)row * DIM + g * 8;
        float4 a = ((const float4*)p)[0];
        float4 b4 = ((const float4*)p)[1];
        v[0] = a.x; v[1] = a.y; v[2] = a.z; v[3] = a.w;
        v[4] = b4.x; v[5] = b4.y; v[6] = b4.z; v[7] = b4.w;
    }
    int o = which ? 3 : 1;
    size_t off = (size_t)row * DIM + g * 8;
    uint4 pk = make_uint4(packh2(v[0], v[1]), packh2(v[2], v[3]),
                          packh2(v[4], v[5]), packh2(v[6], v[7]));
    *(uint4*)&g_Abf[t][o][off] = pk;
}

// ---------------- weight / bias repack ----------------------------------------------
#define W2A_TOT (2 * 3 * 128 * 512)
#define W2B_TOT (2 * 128 * 256)
__global__ void k_repackW(const float* __restrict__ Wl, const float* __restrict__ Wr) {
    int idx = blockIdx.x * blockDim.x + threadIdx.x;
    if (idx < W2A_TOT) {
        int t = idx / (3 * 128 * 512);
        int r = idx % (3 * 128 * 512);
        int ct = r / (128 * 512);
        int r2 = r % (128 * 512);
        int n = r2 / 512;
        int k = r2 % 512;
        float w = 0.f;
        if (!(ct == 2 && k >= 256)) {
            int o = k >> 7, kk = k & 127;
            int gate = ct * 2 + ((o >= 2) ? 1 : 0);
            const float* Wsrc = ((o & 1) == 0) ? Wl : Wr;
            int wi = 1 - t;
            w = Wsrc[((size_t)(gate * 2 + wi) * 128 + kk) * 128 + n];
        }
        g_W2A[t][ct][n * 512 + k] = __float2half_rn(w);
        return;
    }
    int i2 = idx - W2A_TOT;
    if (i2 < W2B_TOT) {
        int t = i2 / (128 * 256);
        int r2 = i2 % (128 * 256);
        int n = r2 / 256;
        int k = r2 % 256;
        int o = k >> 7, kk = k & 127;
        const float* Wsrc = (o == 0) ? Wl : Wr;
        int wi = 1 - t;
        float w = Wsrc[((size_t)(5 * 2 + wi) * 128 + kk) * 128 + n];
        g_W2B[t][n * 256 + k] = __float2half_rn(w);
    }
}

__global__ void k_repack2(const float* __restrict__ b) {
    int idx = blockIdx.x * blockDim.x + threadIdx.x;
    if (idx >= 2 * 128) return;
    int t = idx / 128, c = idx % 128;
    int wi = 1 - t;
    g_bias[t][0][c] = b[(0 * 2 + wi) * 128 + c] + b[(1 * 2 + wi) * 128 + c];
    g_bias[t][1][c] = b[(2 * 2 + wi) * 128 + c] + b[(3 * 2 + wi) * 128 + c];
    g_bias[t][2][c] = b[(4 * 2 + wi) * 128 + c];
    g_bias5[t][c]   = b[(5 * 2 + wi) * 128 + c];
}

// ---------------- fp16 tensor-core GEMM (mma.sync) -----------------------------------
__device__ __forceinline__ void load_tile(uint32_t sa, uint32_t sw,
                                          const __half* Ag, const __half* Wg,
                                          int ldw, int tid) {
#pragma unroll
    for (int i = 0; i < 2; i++) {
        int c = tid * 2 + i;
        int row = c >> 2, q = c & 3;
        uint32_t d = sa + (uint32_t)(row * 80 + q * 16);
        const void* s = Ag + (size_t)row * 128 + q * 8;
        asm volatile("cp.async.cg.shared.global [%0], [%1], 16;" :: "r"(d), "l"(s));
        uint32_t d2 = sw + (uint32_t)(row * 80 + q * 16);
        const void* s2 = Wg + (size_t)row * ldw + q * 8;
        asm volatile("cp.async.cg.shared.global [%0], [%1], 16;" :: "r"(d2), "l"(s2));
    }
    asm volatile("cp.async.commit_group;");
}

template <int PASS>
__global__ void __launch_bounds__(256, 2) k_mma(const float* __restrict__ hu,
                                                const float* __restrict__ hn,
                                                float* __restrict__ out) {
    __shared__ __align__(16) unsigned char sA[2][128 * 80];
    __shared__ __align__(16) unsigned char sW[2][128 * 80];
    const int typ = blockIdx.z, ct = blockIdx.y, tm = blockIdx.x;
    const int tid = threadIdx.x, wid = tid >> 5, lane = tid & 31;
    const int wm = wid & 1, wn = wid >> 1;

    const int NO   = (PASS == 0) ? ((ct < 2) ? 4 : 2) : 2;
    const int NIT  = NO * 4;
    const int ldw  = (PASS == 0) ? 512 : 256;
    const __half* Wrow = (PASS == 0) ? g_W2A[typ][ct] : g_W2B[typ];

    uint32_t sAu[2] = { smem_u32(sA[0]), smem_u32(sA[1]) };
    uint32_t sWu[2] = { smem_u32(sW[0]), smem_u32(sW[1]) };

    float acc[4][4][4];
#pragma unroll
    for (int a = 0; a < 4; a++)
#pragma unroll
        for (int bq = 0; bq < 4; bq++)
#pragma unroll
            for (int cq = 0; cq < 4; cq++) acc[a][bq][cq] = 0.f;

    auto asegp = [&](int s) -> const __half* {
        return (PASS == 0) ? &g_Abf[typ][s][0] : &g_Bbf[typ][s][0];
    };

    {
        const __half* Ag = asegp(0) + (size_t)(tm * 128) * 128;
        load_tile(sAu[0], sWu[0], Ag, Wrow, ldw, tid);
    }

#pragma unroll 1
    for (int kt = 0; kt < NIT; kt++) {
        int bsel = kt & 1;
        if (kt + 1 < NIT) {
            int s = (kt + 1) >> 2, kk = ((kt + 1) & 3) * 32;
            const __half* Ag = asegp(s) + (size_t)(tm * 128) * 128 + kk;
            const __half* Wg = Wrow + s * 128 + kk;
            load_tile(sAu[bsel ^ 1], sWu[bsel ^ 1], Ag, Wg, ldw, tid);
            asm volatile("cp.async.wait_group 1;");
        } else {
            asm volatile("cp.async.wait_group 0;");
        }
        __syncthreads();

        uint32_t aB = sAu[bsel] + (uint32_t)((wm * 64) * 80);
        uint32_t bB = sWu[bsel] + (uint32_t)((wn * 32) * 80);
#pragma unroll
        for (int k16 = 0; k16 < 2; k16++) {
            uint32_t afr[4][4], bfr[2][4];
#pragma unroll
            for (int mt = 0; mt < 4; mt++) {
                uint32_t addr = aB + (uint32_t)((mt * 16 + (lane & 15)) * 80 +
                                                k16 * 32 + (lane >> 4) * 16);
                ldsm4(afr[mt], addr);
            }
#pragma unroll
            for (int np = 0; np < 2; np++) {
                uint32_t addr = bB + (uint32_t)((np * 16 + (lane & 7) + ((lane >> 4) * 8)) * 80 +
                                                k16 * 32 + ((lane >> 3) & 1) * 16);
                ldsm4(bfr[np], addr);
            }
#pragma unroll
            for (int mt = 0; mt < 4; mt++)
#pragma unroll
                for (int nt = 0; nt < 4; nt++)
                    mma16816(acc[mt][nt], afr[mt],
                             bfr[nt >> 1][(nt & 1) * 2], bfr[nt >> 1][(nt & 1) * 2 + 1]);
        }
        __syncthreads();
    }

    // ---------------- epilogue ----------------
    const float* hself = typ ? hn : hu;
    int rowW = tm * 128 + wm * 64;
    int colW = wn * 32;
#pragma unroll
    for (int mt = 0; mt < 4; mt++) {
#pragma unroll
        for (int i = 0; i < 2; i++) {
            int row = rowW + mt * 16 + (lane >> 2) + i * 8;
            if (row >= N_NODES) continue;
#pragma unroll
            for (int nt = 0; nt < 4; nt++) {
                int col = colW + nt * 8 + (lane & 3) * 2;
                size_t off = (size_t)row * DIM + col;
                float v0, v1;
                if (PASS == 0) {
                    const float* bias = g_bias[typ][ct];
                    v0 = acc[mt][nt][i * 2 + 0] + bias[col];
                    v1 = acc[mt][nt][i * 2 + 1] + bias[col + 1];
                    if (ct == 0) {
                        *(float2*)&g_z[typ][off] = make_float2(sigmoidf_(v0), sigmoidf_(v1));
                    } else if (ct == 1) {
                        float2 h2 = *(const float2*)&hself[off];
                        float hr0 = h2.x * sigmoidf_(v0);
                        float hr1 = h2.y * sigmoidf_(v1);
                        *(float2*)&g_hr[typ][off] = make_float2(hr0, hr1);
                        *(uint32_t*)&g_Bbf[typ][1][off] = packh2(hr0, hr1);
                    } else {
                        *(float2*)&g_cx[typ][off] = make_float2(v0, v1);
                    }
                } else {
                    const float* bias = g_bias5[typ];
                    v0 = acc[mt][nt][i * 2 + 0] + bias[col];
                    v1 = acc[mt][nt][i * 2 + 1] + bias[col + 1];
                    float2 cx2 = *(const float2*)&g_cx[typ][off];
                    float2 z2  = *(const float2*)&g_z[typ][off];
                    float2 h2  = *(const float2*)&hself[off];
                    float ht0 = tanhf(cx2.x + v0);
                    float ht1 = tanhf(cx2.y + v1);
                    float2 o2;
                    o2.x = z2.x * h2.x + (1.f - z2.x) * ht0;
                    o2.y = z2.y * h2.y + (1.f - z2.y) * ht1;
                    *(float2*)&out[(size_t)typ * N_NODES * DIM + off] = o2;
                }
            }
        }
    }
}

// ---------------- launch ----------------------------------------------------------------
extern "C" void kernel_launch(void* const* d_in, const int* in_sizes, int n_in,
                              void* d_out, int out_size) {
    const float* x_user = (const float*)d_in[0];
    const float* x_news = (const float*)d_in[1];
    const float* h_user = (const float*)d_in[2];
    const float* h_news = (const float*)d_in[3];
    const float* Wl     = (const float*)d_in[4];
    const float* Wr     = (const float*)d_in[5];
    const float* b      = (const float*)d_in[6];
    const int* src_un   = (const int*)d_in[7];
    const int* dst_un   = (const int*)d_in[8];
    const int* src_nu   = (const int*)d_in[9];
    const int* dst_nu   = (const int*)d_in[10];
    float* out = (float*)d_out;
    const int E = in_sizes[7];

    // CSR build
    k_zero2<<<(N_NODES + 255) / 256, 256>>>();
    k_deg2<<<(E + 255) / 256, 256>>>(dst_un, dst_nu, E);
    k_scan<<<2, 1024>>>();
    k_fill<<<(E + 255) / 256, 256>>>(src_un, dst_un, src_nu, dst_nu, E);

    // weight/bias prep + self-feature conversion (independent)
    k_repackW<<<(W2A_TOT + W2B_TOT + 255) / 256, 256>>>(Wl, Wr);
    k_repack2<<<1, 256>>>(b);
    k_conv_xh<<<(2 * 2 * MPAD * 16 + 255) / 256, 256>>>(x_user, h_user, x_news, h_news);

    // aggregation (gather, fused mean + fp16 convert)
    int ablocks = (MPAD * 32 + 255) / 256;
    k_agg_xh<0><<<ablocks, 256>>>(x_news, h_news);   // user dst <- news sources
    k_agg_xh<1><<<ablocks, 256>>>(x_user, h_user);   // news dst <- user sources

    dim3 gA(NTM, 3, 2);
    k_mma<0><<<gA, 256>>>(h_user, h_news, out);

    k_agg_hr<0><<<ablocks, 256>>>();
    k_agg_hr<1><<<ablocks, 256>>>();

    dim3 gB(NTM, 1, 2);
    k_mma<1><<<gB, 256>>>(h_user, h_news, out);
}

// round 8
// speedup vs baseline: 3.8305x; 1.1252x over previous
#include <cuda_runtime.h>
#include <cuda_fp16.h>
#include <math.h>
#include <stdint.h>

#define N_NODES 50000
#define DIM     128
#define NTM     391
#define MPAD    (NTM * 128)   // 50048, zero-padded rows
#define E_MAX   800000

// ---------------- fp32 scratch ---------------------------------------------------
__device__ __align__(16) float g_z    [2][N_NODES * DIM];
__device__ __align__(16) float g_cx   [2][N_NODES * DIM];
__device__ float g_bias [2][3][DIM];
__device__ float g_bias5[2][DIM];

// ---------------- CSR structures ---------------------------------------------------
__device__ int g_degi[2][N_NODES];
__device__ int g_off [2][N_NODES];
__device__ int g_cur [2][N_NODES];
__device__ int g_srcs[2][E_MAX];

// ---------------- fp16 operands, row-major [MPAD][128] ------------------------------
// A operands o: 0=aggx 1=x 2=aggh 3=h
__device__ __align__(16) __half g_Abf[2][4][(size_t)MPAD * DIM];
// B-pass operands o: 0=agghr 1=hr
__device__ __align__(16) __half g_Bbf[2][2][(size_t)MPAD * DIM];
// packed weights W^T: [n rows 128][k cols]; pass A K=512 (ct=2 uses first 256), pass B K=256
__device__ __align__(16) __half g_W2A[2][3][128 * 512];
__device__ __align__(16) __half g_W2B[2][128 * 256];

// ---------------- helpers ----------------------------------------------------------
__device__ __forceinline__ uint32_t smem_u32(const void* p) {
    uint32_t a;
    asm("{ .reg .u64 t; cvta.to.shared.u64 t, %1; cvt.u32.u64 %0, t; }" : "=r"(a) : "l"(p));
    return a;
}
__device__ __forceinline__ void ldsm4(uint32_t* r, uint32_t addr) {
    asm volatile("ldmatrix.sync.aligned.m8n8.x4.shared.b16 {%0,%1,%2,%3}, [%4];"
                 : "=r"(r[0]), "=r"(r[1]), "=r"(r[2]), "=r"(r[3]) : "r"(addr));
}
__device__ __forceinline__ void mma16816(float* c, const uint32_t* a, uint32_t b0, uint32_t b1) {
    asm volatile(
        "mma.sync.aligned.m16n8k16.row.col.f32.f16.f16.f32 "
        "{%0,%1,%2,%3}, {%4,%5,%6,%7}, {%8,%9}, {%0,%1,%2,%3};"
        : "+f"(c[0]), "+f"(c[1]), "+f"(c[2]), "+f"(c[3])
        : "r"(a[0]), "r"(a[1]), "r"(a[2]), "r"(a[3]), "r"(b0), "r"(b1));
}
__device__ __forceinline__ float sigmoidf_(float v) { return 1.f / (1.f + expf(-v)); }
__device__ __forceinline__ uint32_t packh2(float x, float y) {
    __half2 v = __floats2half2_rn(x, y);
    return *(uint32_t*)&v;
}
__device__ __forceinline__ void h_store4(const float* v, void* dp) {
    *(uint2*)dp = make_uint2(packh2(v[0], v[1]), packh2(v[2], v[3]));
}
// accumulate uint2 (4 halves) into float[4]
__device__ __forceinline__ void acc_h4(float* a, uint2 u) {
    float2 f0 = __half22float2(*(__half2*)&u.x);
    float2 f1 = __half22float2(*(__half2*)&u.y);
    a[0] += f0.x; a[1] += f0.y; a[2] += f1.x; a[3] += f1.y;
}

// ---------------- CSR build ---------------------------------------------------------
__global__ void k_zero2() {
    int i = blockIdx.x * blockDim.x + threadIdx.x;
    if (i < N_NODES) {
        g_degi[0][i] = 0; g_degi[1][i] = 0;
        g_cur[0][i] = 0;  g_cur[1][i] = 0;
    }
}

__global__ void k_deg2(const int* __restrict__ dst_un, const int* __restrict__ dst_nu, int E) {
    int e = blockIdx.x * blockDim.x + threadIdx.x;
    if (e < E) {
        atomicAdd(&g_degi[1][dst_un[e]], 1);
        atomicAdd(&g_degi[0][dst_nu[e]], 1);
    }
}

// one block per type; exclusive scan of degi -> off
__global__ void __launch_bounds__(1024) k_scan() {
    const int t = blockIdx.x;
    __shared__ int wsum[32];
    __shared__ int carry;
    if (threadIdx.x == 0) carry = 0;
    __syncthreads();
    int lane = threadIdx.x & 31, wid = threadIdx.x >> 5;
    for (int base = 0; base < N_NODES; base += 1024) {
        int i = base + threadIdx.x;
        int v = (i < N_NODES) ? g_degi[t][i] : 0;
        int s = v;
#pragma unroll
        for (int o = 1; o < 32; o <<= 1) {
            int u = __shfl_up_sync(0xFFFFFFFFu, s, o);
            if (lane >= o) s += u;
        }
        if (lane == 31) wsum[wid] = s;
        __syncthreads();
        if (wid == 0) {
            int ws = wsum[lane];
#pragma unroll
            for (int o = 1; o < 32; o <<= 1) {
                int u = __shfl_up_sync(0xFFFFFFFFu, ws, o);
                if (lane >= o) ws += u;
            }
            wsum[lane] = ws;
        }
        __syncthreads();
        int excl = carry + (wid > 0 ? wsum[wid - 1] : 0) + s - v;
        if (i < N_NODES) g_off[t][i] = excl;
        int total = wsum[31];
        __syncthreads();
        if (threadIdx.x == 0) carry += total;
        __syncthreads();
    }
}

__global__ void k_fill(const int* __restrict__ src_un, const int* __restrict__ dst_un,
                       const int* __restrict__ src_nu, const int* __restrict__ dst_nu, int E) {
    int e = blockIdx.x * blockDim.x + threadIdx.x;
    if (e >= E) return;
    int d1 = dst_un[e];
    int p1 = atomicAdd(&g_cur[1][d1], 1);
    g_srcs[1][g_off[1][d1] + p1] = src_un[e];
    int d0 = dst_nu[e];
    int p0 = atomicAdd(&g_cur[0][d0], 1);
    g_srcs[0][g_off[0][d0] + p0] = src_nu[e];
}

// ---------------- gather aggregation from fp16 tables: warp per dst row ---------------
// source features: fp16 x/h of the OTHER node type (g_Abf[1-TYP][1], [3])
template <int TYP>
__global__ void k_agg_xh() {
    int w = (blockIdx.x * blockDim.x + threadIdx.x) >> 5;
    int lane = threadIdx.x & 31;
    if (w >= MPAD) return;
    int n = 0, beg = 0;
    if (w < N_NODES) { n = g_degi[TYP][w]; beg = g_off[TYP][w]; }
    const int* sp = &g_srcs[TYP][beg];
    const __half* xs = g_Abf[1 - TYP][1];
    const __half* hs = g_Abf[1 - TYP][3];
    float ax[4] = {0.f, 0.f, 0.f, 0.f};
    float ah[4] = {0.f, 0.f, 0.f, 0.f};
    int co = lane * 4;
    int j = 0;
    for (; j + 4 <= n; j += 4) {
        int s0 = __ldg(sp + j), s1 = __ldg(sp + j + 1);
        int s2 = __ldg(sp + j + 2), s3 = __ldg(sp + j + 3);
        uint2 x0 = *(const uint2*)(xs + (size_t)s0 * DIM + co);
        uint2 x1 = *(const uint2*)(xs + (size_t)s1 * DIM + co);
        uint2 x2 = *(const uint2*)(xs + (size_t)s2 * DIM + co);
        uint2 x3 = *(const uint2*)(xs + (size_t)s3 * DIM + co);
        uint2 h0 = *(const uint2*)(hs + (size_t)s0 * DIM + co);
        uint2 h1 = *(const uint2*)(hs + (size_t)s1 * DIM + co);
        uint2 h2 = *(const uint2*)(hs + (size_t)s2 * DIM + co);
        uint2 h3 = *(const uint2*)(hs + (size_t)s3 * DIM + co);
        acc_h4(ax, x0); acc_h4(ax, x1); acc_h4(ax, x2); acc_h4(ax, x3);
        acc_h4(ah, h0); acc_h4(ah, h1); acc_h4(ah, h2); acc_h4(ah, h3);
    }
    for (; j < n; j++) {
        int s = __ldg(sp + j);
        uint2 x0 = *(const uint2*)(xs + (size_t)s * DIM + co);
        uint2 h0 = *(const uint2*)(hs + (size_t)s * DIM + co);
        acc_h4(ax, x0); acc_h4(ah, h0);
    }
    float inv = 1.f / (float)max(n, 1);
#pragma unroll
    for (int i = 0; i < 4; i++) { ax[i] *= inv; ah[i] *= inv; }
    size_t off = (size_t)w * DIM + co;
    h_store4(ax, &g_Abf[TYP][0][off]);
    h_store4(ah, &g_Abf[TYP][2][off]);
}

// source features: fp16 hr of the OTHER node type (g_Bbf[1-TYP][1])
template <int TYP>
__global__ void k_agg_hr() {
    int w = (blockIdx.x * blockDim.x + threadIdx.x) >> 5;
    int lane = threadIdx.x & 31;
    if (w >= MPAD) return;
    int n = 0, beg = 0;
    if (w < N_NODES) { n = g_degi[TYP][w]; beg = g_off[TYP][w]; }
    const int* sp = &g_srcs[TYP][beg];
    const __half* fs = g_Bbf[1 - TYP][1];
    float a[4] = {0.f, 0.f, 0.f, 0.f};
    int co = lane * 4;
    int j = 0;
    for (; j + 4 <= n; j += 4) {
        int s0 = __ldg(sp + j), s1 = __ldg(sp + j + 1);
        int s2 = __ldg(sp + j + 2), s3 = __ldg(sp + j + 3);
        uint2 v0 = *(const uint2*)(fs + (size_t)s0 * DIM + co);
        uint2 v1 = *(const uint2*)(fs + (size_t)s1 * DIM + co);
        uint2 v2 = *(const uint2*)(fs + (size_t)s2 * DIM + co);
        uint2 v3 = *(const uint2*)(fs + (size_t)s3 * DIM + co);
        acc_h4(a, v0); acc_h4(a, v1); acc_h4(a, v2); acc_h4(a, v3);
    }
    for (; j < n; j++) {
        int s = __ldg(sp + j);
        uint2 v0 = *(const uint2*)(fs + (size_t)s * DIM + co);
        acc_h4(a, v0);
    }
    float inv = 1.f / (float)max(n, 1);
#pragma unroll
    for (int i = 0; i < 4; i++) a[i] *= inv;
    size_t off = (size_t)w * DIM + co;
    h_store4(a, &g_Bbf[TYP][0][off]);
}

// ---------------- x/h -> fp16 (GEMM self operands) ------------------------------------
__global__ void k_conv_xh(const float* __restrict__ xu, const float* __restrict__ hu,
                          const float* __restrict__ xn, const float* __restrict__ hn) {
    int idx = blockIdx.x * blockDim.x + threadIdx.x;
    if (idx >= 2 * 2 * MPAD * 16) return;
    int g = idx & 15;
    int rid = idx >> 4;
    int row = rid % MPAD;
    int rest = rid / MPAD;
    int which = rest & 1;   // 0: x -> o=1, 1: h -> o=3
    int t = rest >> 1;
    float v[8] = {0, 0, 0, 0, 0, 0, 0, 0};
    if (row < N_NODES) {
        const float* src = (t == 0) ? (which ? hu : xu) : (which ? hn : xn);
        const float* p = src + (size_t)row * DIM + g * 8;
        float4 a = ((const float4*)p)[0];
        float4 b4 = ((const float4*)p)[1];
        v[0] = a.x; v[1] = a.y; v[2] = a.z; v[3] = a.w;
        v[4] = b4.x; v[5] = b4.y; v[6] = b4.z; v[7] = b4.w;
    }
    int o = which ? 3 : 1;
    size_t off = (size_t)row * DIM + g * 8;
    uint4 pk = make_uint4(packh2(v[0], v[1]), packh2(v[2], v[3]),
                          packh2(v[4], v[5]), packh2(v[6], v[7]));
    *(uint4*)&g_Abf[t][o][off] = pk;
}

// ---------------- weight / bias repack ----------------------------------------------
#define W2A_TOT (2 * 3 * 128 * 512)
#define W2B_TOT (2 * 128 * 256)
__global__ void k_repackW(const float* __restrict__ Wl, const float* __restrict__ Wr) {
    int idx = blockIdx.x * blockDim.x + threadIdx.x;
    if (idx < W2A_TOT) {
        int t = idx / (3 * 128 * 512);
        int r = idx % (3 * 128 * 512);
        int ct = r / (128 * 512);
        int r2 = r % (128 * 512);
        int n = r2 / 512;
        int k = r2 % 512;
        float w = 0.f;
        if (!(ct == 2 && k >= 256)) {
            int o = k >> 7, kk = k & 127;
            int gate = ct * 2 + ((o >= 2) ? 1 : 0);
            const float* Wsrc = ((o & 1) == 0) ? Wl : Wr;
            int wi = 1 - t;
            w = Wsrc[((size_t)(gate * 2 + wi) * 128 + kk) * 128 + n];
        }
        g_W2A[t][ct][n * 512 + k] = __float2half_rn(w);
        return;
    }
    int i2 = idx - W2A_TOT;
    if (i2 < W2B_TOT) {
        int t = i2 / (128 * 256);
        int r2 = i2 % (128 * 256);
        int n = r2 / 256;
        int k = r2 % 256;
        int o = k >> 7, kk = k & 127;
        const float* Wsrc = (o == 0) ? Wl : Wr;
        int wi = 1 - t;
        float w = Wsrc[((size_t)(5 * 2 + wi) * 128 + kk) * 128 + n];
        g_W2B[t][n * 256 + k] = __float2half_rn(w);
    }
}

__global__ void k_repack2(const float* __restrict__ b) {
    int idx = blockIdx.x * blockDim.x + threadIdx.x;
    if (idx >= 2 * 128) return;
    int t = idx / 128, c = idx % 128;
    int wi = 1 - t;
    g_bias[t][0][c] = b[(0 * 2 + wi) * 128 + c] + b[(1 * 2 + wi) * 128 + c];
    g_bias[t][1][c] = b[(2 * 2 + wi) * 128 + c] + b[(3 * 2 + wi) * 128 + c];
    g_bias[t][2][c] = b[(4 * 2 + wi) * 128 + c];
    g_bias5[t][c]   = b[(5 * 2 + wi) * 128 + c];
}

// ---------------- fp16 tensor-core GEMM (mma.sync) -----------------------------------
__device__ __forceinline__ void load_tile(uint32_t sa, uint32_t sw,
                                          const __half* Ag, const __half* Wg,
                                          int ldw, int tid) {
#pragma unroll
    for (int i = 0; i < 2; i++) {
        int c = tid * 2 + i;
        int row = c >> 2, q = c & 3;
        uint32_t d = sa + (uint32_t)(row * 80 + q * 16);
        const void* s = Ag + (size_t)row * 128 + q * 8;
        asm volatile("cp.async.cg.shared.global [%0], [%1], 16;" :: "r"(d), "l"(s));
        uint32_t d2 = sw + (uint32_t)(row * 80 + q * 16);
        const void* s2 = Wg + (size_t)row * ldw + q * 8;
        asm volatile("cp.async.cg.shared.global [%0], [%1], 16;" :: "r"(d2), "l"(s2));
    }
    asm volatile("cp.async.commit_group;");
}

template <int PASS>
__global__ void __launch_bounds__(256, 2) k_mma(const float* __restrict__ hu,
                                                const float* __restrict__ hn,
                                                float* __restrict__ out) {
    __shared__ __align__(16) unsigned char sA[2][128 * 80];
    __shared__ __align__(16) unsigned char sW[2][128 * 80];
    const int typ = blockIdx.z, ct = blockIdx.y, tm = blockIdx.x;
    const int tid = threadIdx.x, wid = tid >> 5, lane = tid & 31;
    const int wm = wid & 1, wn = wid >> 1;

    const int NO   = (PASS == 0) ? ((ct < 2) ? 4 : 2) : 2;
    const int NIT  = NO * 4;
    const int ldw  = (PASS == 0) ? 512 : 256;
    const __half* Wrow = (PASS == 0) ? g_W2A[typ][ct] : g_W2B[typ];

    uint32_t sAu[2] = { smem_u32(sA[0]), smem_u32(sA[1]) };
    uint32_t sWu[2] = { smem_u32(sW[0]), smem_u32(sW[1]) };

    float acc[4][4][4];
#pragma unroll
    for (int a = 0; a < 4; a++)
#pragma unroll
        for (int bq = 0; bq < 4; bq++)
#pragma unroll
            for (int cq = 0; cq < 4; cq++) acc[a][bq][cq] = 0.f;

    auto asegp = [&](int s) -> const __half* {
        return (PASS == 0) ? &g_Abf[typ][s][0] : &g_Bbf[typ][s][0];
    };

    {
        const __half* Ag = asegp(0) + (size_t)(tm * 128) * 128;
        load_tile(sAu[0], sWu[0], Ag, Wrow, ldw, tid);
    }

#pragma unroll 1
    for (int kt = 0; kt < NIT; kt++) {
        int bsel = kt & 1;
        if (kt + 1 < NIT) {
            int s = (kt + 1) >> 2, kk = ((kt + 1) & 3) * 32;
            const __half* Ag = asegp(s) + (size_t)(tm * 128) * 128 + kk;
            const __half* Wg = Wrow + s * 128 + kk;
            load_tile(sAu[bsel ^ 1], sWu[bsel ^ 1], Ag, Wg, ldw, tid);
            asm volatile("cp.async.wait_group 1;");
        } else {
            asm volatile("cp.async.wait_group 0;");
        }
        __syncthreads();

        uint32_t aB = sAu[bsel] + (uint32_t)((wm * 64) * 80);
        uint32_t bB = sWu[bsel] + (uint32_t)((wn * 32) * 80);
#pragma unroll
        for (int k16 = 0; k16 < 2; k16++) {
            uint32_t afr[4][4], bfr[2][4];
#pragma unroll
            for (int mt = 0; mt < 4; mt++) {
                uint32_t addr = aB + (uint32_t)((mt * 16 + (lane & 15)) * 80 +
                                                k16 * 32 + (lane >> 4) * 16);
                ldsm4(afr[mt], addr);
            }
#pragma unroll
            for (int np = 0; np < 2; np++) {
                uint32_t addr = bB + (uint32_t)((np * 16 + (lane & 7) + ((lane >> 4) * 8)) * 80 +
                                                k16 * 32 + ((lane >> 3) & 1) * 16);
                ldsm4(bfr[np], addr);
            }
#pragma unroll
            for (int mt = 0; mt < 4; mt++)
#pragma unroll
                for (int nt = 0; nt < 4; nt++)
                    mma16816(acc[mt][nt], afr[mt],
                             bfr[nt >> 1][(nt & 1) * 2], bfr[nt >> 1][(nt & 1) * 2 + 1]);
        }
        __syncthreads();
    }

    // ---------------- epilogue ----------------
    const float* hself = typ ? hn : hu;
    int rowW = tm * 128 + wm * 64;
    int colW = wn * 32;
#pragma unroll
    for (int mt = 0; mt < 4; mt++) {
#pragma unroll
        for (int i = 0; i < 2; i++) {
            int row = rowW + mt * 16 + (lane >> 2) + i * 8;
            if (row >= N_NODES) continue;
#pragma unroll
            for (int nt = 0; nt < 4; nt++) {
                int col = colW + nt * 8 + (lane & 3) * 2;
                size_t off = (size_t)row * DIM + col;
                float v0, v1;
                if (PASS == 0) {
                    const float* bias = g_bias[typ][ct];
                    v0 = acc[mt][nt][i * 2 + 0] + bias[col];
                    v1 = acc[mt][nt][i * 2 + 1] + bias[col + 1];
                    if (ct == 0) {
                        *(float2*)&g_z[typ][off] = make_float2(sigmoidf_(v0), sigmoidf_(v1));
                    } else if (ct == 1) {
                        float2 h2 = *(const float2*)&hself[off];
                        float hr0 = h2.x * sigmoidf_(v0);
                        float hr1 = h2.y * sigmoidf_(v1);
                        *(uint32_t*)&g_Bbf[typ][1][off] = packh2(hr0, hr1);
                    } else {
                        *(float2*)&g_cx[typ][off] = make_float2(v0, v1);
                    }
                } else {
                    const float* bias = g_bias5[typ];
                    v0 = acc[mt][nt][i * 2 + 0] + bias[col];
                    v1 = acc[mt][nt][i * 2 + 1] + bias[col + 1];
                    float2 cx2 = *(const float2*)&g_cx[typ][off];
                    float2 z2  = *(const float2*)&g_z[typ][off];
                    float2 h2  = *(const float2*)&hself[off];
                    float ht0 = tanhf(cx2.x + v0);
                    float ht1 = tanhf(cx2.y + v1);
                    float2 o2;
                    o2.x = z2.x * h2.x + (1.f - z2.x) * ht0;
                    o2.y = z2.y * h2.y + (1.f - z2.y) * ht1;
                    *(float2*)&out[(size_t)typ * N_NODES * DIM + off] = o2;
                }
            }
        }
    }
}

// ---------------- launch ----------------------------------------------------------------
extern "C" void kernel_launch(void* const* d_in, const int* in_sizes, int n_in,
                              void* d_out, int out_size) {
    const float* x_user = (const float*)d_in[0];
    const float* x_news = (const float*)d_in[1];
    const float* h_user = (const float*)d_in[2];
    const float* h_news = (const float*)d_in[3];
    const float* Wl     = (const float*)d_in[4];
    const float* Wr     = (const float*)d_in[5];
    const float* b      = (const float*)d_in[6];
    const int* src_un   = (const int*)d_in[7];
    const int* dst_un   = (const int*)d_in[8];
    const int* src_nu   = (const int*)d_in[9];
    const int* dst_nu   = (const int*)d_in[10];
    float* out = (float*)d_out;
    const int E = in_sizes[7];

    // CSR build
    k_zero2<<<(N_NODES + 255) / 256, 256>>>();
    k_deg2<<<(E + 255) / 256, 256>>>(dst_un, dst_nu, E);
    k_scan<<<2, 1024>>>();
    k_fill<<<(E + 255) / 256, 256>>>(src_un, dst_un, src_nu, dst_nu, E);

    // weight/bias prep + self-feature conversion
    k_repackW<<<(W2A_TOT + W2B_TOT + 255) / 256, 256>>>(Wl, Wr);
    k_repack2<<<1, 256>>>(b);
    k_conv_xh<<<(2 * 2 * MPAD * 16 + 255) / 256, 256>>>(x_user, h_user, x_news, h_news);

    // aggregation from fp16 tables (gather, fused mean + fp16 store)
    int ablocks = (MPAD * 32 + 255) / 256;
    k_agg_xh<0><<<ablocks, 256>>>();   // user dst <- news fp16 x/h
    k_agg_xh<1><<<ablocks, 256>>>();   // news dst <- user fp16 x/h

    dim3 gA(NTM, 3, 2);
    k_mma<0><<<gA, 256>>>(h_user, h_news, out);

    k_agg_hr<0><<<ablocks, 256>>>();
    k_agg_hr<1><<<ablocks, 256>>>();

    dim3 gB(NTM, 1, 2);
    k_mma<1><<<gB, 256>>>(h_user, h_news, out);
}